// round 1
// baseline (speedup 1.0000x reference)
#include <cuda_runtime.h>
#include <cstdint>
#include <math.h>

// Problem constants
#define BB 2
#define LL 2048
#define DDIM 1024
#define HH 16
#define HDIM 64
#define MM (BB*LL)          // 4096 rows
#define WIN 512
#define DIL 2

// Scratch (device globals; no allocation allowed)
__device__ float g_h[(size_t)MM*DDIM];          // LN output (reused for LN2)
__device__ float g_qkv[(size_t)MM*3*DDIM];      // QKV
__device__ float g_attn[(size_t)MM*DDIM];       // attention output (B,L,D)
__device__ float g_x1[(size_t)MM*DDIM];         // x + attn_out @ Wout
__device__ float g_f[(size_t)MM*4*DDIM];        // FFN hidden

// ---------------------------------------------------------------------------
// LayerNorm: one block (256 threads) per row of 1024 floats
// ---------------------------------------------------------------------------
__global__ void ln_kernel(const float* __restrict__ x, const float* __restrict__ g,
                          const float* __restrict__ b, float* __restrict__ out) {
    int row = blockIdx.x;
    int t = threadIdx.x;
    const float4 xv = reinterpret_cast<const float4*>(x + (size_t)row * DDIM)[t];

    __shared__ float warp_s[8], warp_q[8];
    __shared__ float s_mu, s_r;

    float s = xv.x + xv.y + xv.z + xv.w;
    float q = xv.x*xv.x + xv.y*xv.y + xv.z*xv.z + xv.w*xv.w;
#pragma unroll
    for (int o = 16; o; o >>= 1) {
        s += __shfl_xor_sync(~0u, s, o);
        q += __shfl_xor_sync(~0u, q, o);
    }
    if ((t & 31) == 0) { warp_s[t >> 5] = s; warp_q[t >> 5] = q; }
    __syncthreads();
    if (t == 0) {
        float S = 0.f, Q = 0.f;
#pragma unroll
        for (int i = 0; i < 8; i++) { S += warp_s[i]; Q += warp_q[i]; }
        float mu = S * (1.0f / DDIM);
        float var = Q * (1.0f / DDIM) - mu * mu;
        s_mu = mu;
        s_r = rsqrtf(var + 1e-5f);
    }
    __syncthreads();
    float mu = s_mu, r = s_r;
    float4 gv = reinterpret_cast<const float4*>(g)[t];
    float4 bv = reinterpret_cast<const float4*>(b)[t];
    float4 o;
    o.x = (xv.x - mu) * r * gv.x + bv.x;
    o.y = (xv.y - mu) * r * gv.y + bv.y;
    o.z = (xv.z - mu) * r * gv.z + bv.z;
    o.w = (xv.w - mu) * r * gv.w + bv.w;
    reinterpret_cast<float4*>(out + (size_t)row * DDIM)[t] = o;
}

// ---------------------------------------------------------------------------
// TF32 GEMM: C[M,N] = A[M,K] @ W[K,N] + bias, with fused epilogues
// EPI: 0 = bias only, 1 = bias + residual, 2 = bias + exact GELU
// Block tile 128x128x16, 256 threads, warp tile 64x32 via m16n8k8 tf32 mma.
// ---------------------------------------------------------------------------
#define BM 128
#define BN 128
#define BK 16
#define SPAD 4

__device__ __forceinline__ uint32_t f2tf(float x) {
    uint32_t r;
    asm("cvt.rna.tf32.f32 %0, %1;" : "=r"(r) : "f"(x));
    return r;
}

__device__ __forceinline__ void mma_tf32(float d[4], const uint32_t a[4],
                                         const uint32_t b[2], const float c[4]) {
    asm volatile(
        "mma.sync.aligned.m16n8k8.row.col.f32.tf32.tf32.f32 "
        "{%0,%1,%2,%3}, {%4,%5,%6,%7}, {%8,%9}, {%10,%11,%12,%13};\n"
        : "=f"(d[0]), "=f"(d[1]), "=f"(d[2]), "=f"(d[3])
        : "r"(a[0]), "r"(a[1]), "r"(a[2]), "r"(a[3]),
          "r"(b[0]), "r"(b[1]),
          "f"(c[0]), "f"(c[1]), "f"(c[2]), "f"(c[3]));
}

__device__ __forceinline__ float gelu_exact(float x) {
    return 0.5f * x * (1.0f + erff(x * 0.70710678118654752f));
}

template <int EPI>
__global__ void __launch_bounds__(256, 2)
gemm_tf32(const float* __restrict__ A, const float* __restrict__ W,
          const float* __restrict__ bias, const float* __restrict__ res,
          float* __restrict__ C, int M, int N, int K) {
    __shared__ uint32_t As[BK][BM + SPAD];
    __shared__ uint32_t Bs[BK][BN + SPAD];

    int tid = threadIdx.x;
    int bm = blockIdx.y, bn = blockIdx.x;
    int warp = tid >> 5, lane = tid & 31;
    int wm = warp & 1;    // 2 warps along M  -> 64 rows each
    int wn = warp >> 1;   // 4 warps along N  -> 32 cols each

    const int m0 = bm * BM, n0 = bn * BN;

    float acc[4][4][4];
#pragma unroll
    for (int i = 0; i < 4; i++)
#pragma unroll
        for (int j = 0; j < 4; j++)
#pragma unroll
            for (int k = 0; k < 4; k++) acc[i][j][k] = 0.f;

    for (int k0 = 0; k0 < K; k0 += BK) {
        // Load A tile (128x16) and W tile (16x128) into shared as tf32
#pragma unroll
        for (int i = 0; i < 2; i++) {
            int f = tid + i * 256;
            // A: row-major [M,K]; transpose into As[k][m]
            int ra = f >> 2, ca = (f & 3) * 4;
            float4 va = *reinterpret_cast<const float4*>(
                A + (size_t)(m0 + ra) * K + k0 + ca);
            As[ca + 0][ra] = f2tf(va.x);
            As[ca + 1][ra] = f2tf(va.y);
            As[ca + 2][ra] = f2tf(va.z);
            As[ca + 3][ra] = f2tf(va.w);
            // W: row-major [K,N]; keep as Bs[k][n]
            int rb = f >> 5, cb = (f & 31) * 4;
            float4 vb = *reinterpret_cast<const float4*>(
                W + (size_t)(k0 + rb) * N + n0 + cb);
            uint4 ub;
            ub.x = f2tf(vb.x); ub.y = f2tf(vb.y);
            ub.z = f2tf(vb.z); ub.w = f2tf(vb.w);
            *reinterpret_cast<uint4*>(&Bs[rb][cb]) = ub;
        }
        __syncthreads();

#pragma unroll
        for (int ks = 0; ks < BK; ks += 8) {
            uint32_t a[4][4], b[4][2];
            int kr = ks + (lane & 3);
            int mrow = (lane >> 2);
#pragma unroll
            for (int fm = 0; fm < 4; fm++) {
                int mb = wm * 64 + fm * 16 + mrow;
                a[fm][0] = As[kr][mb];
                a[fm][1] = As[kr][mb + 8];
                a[fm][2] = As[kr + 4][mb];
                a[fm][3] = As[kr + 4][mb + 8];
            }
            int nb = wn * 32 + (lane >> 2);
#pragma unroll
            for (int fn = 0; fn < 4; fn++) {
                b[fn][0] = Bs[kr][nb + fn * 8];
                b[fn][1] = Bs[kr + 4][nb + fn * 8];
            }
#pragma unroll
            for (int fm = 0; fm < 4; fm++)
#pragma unroll
                for (int fn = 0; fn < 4; fn++)
                    mma_tf32(acc[fm][fn], a[fm], b[fn], acc[fm][fn]);
        }
        __syncthreads();
    }

    // Epilogue
#pragma unroll
    for (int fm = 0; fm < 4; fm++) {
#pragma unroll
        for (int fn = 0; fn < 4; fn++) {
            int mr = m0 + wm * 64 + fm * 16 + (lane >> 2);
            int nc = n0 + wn * 32 + fn * 8 + ((lane & 3) << 1);
            float bx = bias[nc], by = bias[nc + 1];
            float v0 = acc[fm][fn][0] + bx;
            float v1 = acc[fm][fn][1] + by;
            float v2 = acc[fm][fn][2] + bx;
            float v3 = acc[fm][fn][3] + by;
            if (EPI == 1) {
                v0 += res[(size_t)mr * N + nc];
                v1 += res[(size_t)mr * N + nc + 1];
                v2 += res[(size_t)(mr + 8) * N + nc];
                v3 += res[(size_t)(mr + 8) * N + nc + 1];
            } else if (EPI == 2) {
                v0 = gelu_exact(v0); v1 = gelu_exact(v1);
                v2 = gelu_exact(v2); v3 = gelu_exact(v3);
            }
            float2 p0 = make_float2(v0, v1);
            float2 p1 = make_float2(v2, v3);
            *reinterpret_cast<float2*>(C + (size_t)mr * N + nc) = p0;
            *reinterpret_cast<float2*>(C + (size_t)(mr + 8) * N + nc) = p1;
        }
    }
}

// ---------------------------------------------------------------------------
// Dilated causal windowed attention: one warp per query, online softmax.
// qkv layout: row (b*L + l), col = s*D + h*64 + d  (s=0:q, 1:k, 2:v)
// Keys for query l: l - 2j, j = 0..min(256, l/2)
// ---------------------------------------------------------------------------
__global__ void attn_kernel(const float* __restrict__ qkv, float* __restrict__ out) {
    int gw = (blockIdx.x * blockDim.x + threadIdx.x) >> 5;
    int lane = threadIdx.x & 31;
    int ql = gw & (LL - 1);
    int h = (gw >> 11) & (HH - 1);
    int b = gw >> 15;

    const float* qp = qkv + ((size_t)(b * LL + ql)) * (3 * DDIM) + h * HDIM;
    float q0 = qp[lane] * 0.125f;          // 1/sqrt(64)
    float q1 = qp[lane + 32] * 0.125f;

    float m = -1e30f, l = 0.f, o0 = 0.f, o1 = 0.f;
    int nk = min(WIN / DIL, ql / DIL);     // inclusive j range

    for (int j = 0; j <= nk; j++) {
        int lk = ql - DIL * j;
        const float* kp = qkv + ((size_t)(b * LL + lk)) * (3 * DDIM) + DDIM + h * HDIM;
        float s = q0 * kp[lane] + q1 * kp[lane + 32];
#pragma unroll
        for (int o = 16; o; o >>= 1) s += __shfl_xor_sync(~0u, s, o);
        const float* vp = kp + DDIM;
        float mn = fmaxf(m, s);
        float cf = __expf(m - mn);
        float p = __expf(s - mn);
        l = l * cf + p;
        o0 = o0 * cf + p * vp[lane];
        o1 = o1 * cf + p * vp[lane + 32];
        m = mn;
    }
    float inv = 1.0f / l;
    float* op = out + ((size_t)(b * LL + ql)) * DDIM + h * HDIM;
    op[lane] = o0 * inv;
    op[lane + 32] = o1 * inv;
}

// ---------------------------------------------------------------------------
// Launch
// ---------------------------------------------------------------------------
extern "C" void kernel_launch(void* const* d_in, const int* in_sizes, int n_in,
                              void* d_out, int out_size) {
    const float* x     = (const float*)d_in[0];
    const float* ln1_g = (const float*)d_in[1];
    const float* ln1_b = (const float*)d_in[2];
    const float* Wqkv  = (const float*)d_in[3];
    const float* bqkv  = (const float*)d_in[4];
    const float* Wout  = (const float*)d_in[5];
    const float* bout  = (const float*)d_in[6];
    const float* ln2_g = (const float*)d_in[7];
    const float* ln2_b = (const float*)d_in[8];
    const float* W1    = (const float*)d_in[9];
    const float* b1    = (const float*)d_in[10];
    const float* W2    = (const float*)d_in[11];
    const float* b2    = (const float*)d_in[12];
    float* out = (float*)d_out;

    float *h, *qkv, *attn, *x1, *f;
    cudaGetSymbolAddress((void**)&h, g_h);
    cudaGetSymbolAddress((void**)&qkv, g_qkv);
    cudaGetSymbolAddress((void**)&attn, g_attn);
    cudaGetSymbolAddress((void**)&x1, g_x1);
    cudaGetSymbolAddress((void**)&f, g_f);

    // 1. LN1
    ln_kernel<<<MM, 256>>>(x, ln1_g, ln1_b, h);
    // 2. QKV = h @ Wqkv + bqkv          [4096,1024]x[1024,3072]
    gemm_tf32<0><<<dim3(3 * DDIM / BN, MM / BM), 256>>>(h, Wqkv, bqkv, nullptr,
                                                        qkv, MM, 3 * DDIM, DDIM);
    // 3. attention
    attn_kernel<<<(BB * HH * LL) / 8, 256>>>(qkv, attn);
    // 4. x1 = x + attn @ Wout + bout    [4096,1024]x[1024,1024]
    gemm_tf32<1><<<dim3(DDIM / BN, MM / BM), 256>>>(attn, Wout, bout, x,
                                                    x1, MM, DDIM, DDIM);
    // 5. LN2
    ln_kernel<<<MM, 256>>>(x1, ln2_g, ln2_b, h);
    // 6. f = gelu(h @ W1 + b1)          [4096,1024]x[1024,4096]
    gemm_tf32<2><<<dim3(4 * DDIM / BN, MM / BM), 256>>>(h, W1, b1, nullptr,
                                                        f, MM, 4 * DDIM, DDIM);
    // 7. out = x1 + f @ W2 + b2         [4096,4096]x[4096,1024]
    gemm_tf32<1><<<dim3(DDIM / BN, MM / BM), 256>>>(f, W2, b2, x1,
                                                    out, MM, DDIM, 4 * DDIM);
}

// round 2
// speedup vs baseline: 1.0955x; 1.0955x over previous
#include <cuda_runtime.h>
#include <cstdint>
#include <math.h>

// Problem constants
#define BB 2
#define LL 2048
#define DDIM 1024
#define HH 16
#define HDIM 64
#define MM (BB*LL)          // 4096 rows
#define WIN 512
#define DIL 2

// Scratch (device globals; no allocation allowed)
__device__ float g_h[(size_t)MM*DDIM];          // LN output (reused for LN2)
__device__ float g_qkv[(size_t)MM*3*DDIM];      // QKV
__device__ float g_attn[(size_t)MM*DDIM];       // attention output (B,L,D)
__device__ float g_x1[(size_t)MM*DDIM];         // x + attn_out @ Wout
__device__ float g_f[(size_t)MM*4*DDIM];        // FFN hidden

__device__ __forceinline__ uint32_t f2tf(float x) {
    uint32_t r;
    asm("cvt.rna.tf32.f32 %0, %1;" : "=r"(r) : "f"(x));
    return r;
}

__device__ __forceinline__ void mma_tf32(float d[4], const uint32_t a[4],
                                         const uint32_t b[2], const float c[4]) {
    asm volatile(
        "mma.sync.aligned.m16n8k8.row.col.f32.tf32.tf32.f32 "
        "{%0,%1,%2,%3}, {%4,%5,%6,%7}, {%8,%9}, {%10,%11,%12,%13};\n"
        : "=f"(d[0]), "=f"(d[1]), "=f"(d[2]), "=f"(d[3])
        : "r"(a[0]), "r"(a[1]), "r"(a[2]), "r"(a[3]),
          "r"(b[0]), "r"(b[1]),
          "f"(c[0]), "f"(c[1]), "f"(c[2]), "f"(c[3]));
}

__device__ __forceinline__ float gelu_exact(float x) {
    return 0.5f * x * (1.0f + erff(x * 0.70710678118654752f));
}

// ---------------------------------------------------------------------------
// LayerNorm: one block (256 threads) per row of 1024 floats
// ---------------------------------------------------------------------------
__global__ void ln_kernel(const float* __restrict__ x, const float* __restrict__ g,
                          const float* __restrict__ b, float* __restrict__ out) {
    int row = blockIdx.x;
    int t = threadIdx.x;
    const float4 xv = reinterpret_cast<const float4*>(x + (size_t)row * DDIM)[t];

    __shared__ float warp_s[8], warp_q[8];
    __shared__ float s_mu, s_r;

    float s = xv.x + xv.y + xv.z + xv.w;
    float q = xv.x*xv.x + xv.y*xv.y + xv.z*xv.z + xv.w*xv.w;
#pragma unroll
    for (int o = 16; o; o >>= 1) {
        s += __shfl_xor_sync(~0u, s, o);
        q += __shfl_xor_sync(~0u, q, o);
    }
    if ((t & 31) == 0) { warp_s[t >> 5] = s; warp_q[t >> 5] = q; }
    __syncthreads();
    if (t == 0) {
        float S = 0.f, Q = 0.f;
#pragma unroll
        for (int i = 0; i < 8; i++) { S += warp_s[i]; Q += warp_q[i]; }
        float mu = S * (1.0f / DDIM);
        float var = Q * (1.0f / DDIM) - mu * mu;
        s_mu = mu;
        s_r = rsqrtf(var + 1e-5f);
    }
    __syncthreads();
    float mu = s_mu, r = s_r;
    float4 gv = reinterpret_cast<const float4*>(g)[t];
    float4 bv = reinterpret_cast<const float4*>(b)[t];
    float4 o;
    o.x = (xv.x - mu) * r * gv.x + bv.x;
    o.y = (xv.y - mu) * r * gv.y + bv.y;
    o.z = (xv.z - mu) * r * gv.z + bv.z;
    o.w = (xv.w - mu) * r * gv.w + bv.w;
    reinterpret_cast<float4*>(out + (size_t)row * DDIM)[t] = o;
}

// ---------------------------------------------------------------------------
// TF32 GEMM v2: double-buffered smem, swizzled layouts, vectorized LDS.
// C[M,N] = A[M,K] @ W[K,N] + bias; EPI: 0=bias, 1=bias+residual, 2=bias+GELU
// Block 128x128x16, 256 threads, warp tile 64x32 via m16n8k8 tf32 mma.
// smem A layout: As[k][m'] with m' = (m&7)*16 + (m>>3)   (m in 0..127)
// smem B layout: Bs[k][n'] with n' = (n&7)*16 + (n>>3)
// ---------------------------------------------------------------------------
#define BM 128
#define BN 128
#define BK 16
#define GP 132   // row pitch (128 + 4) -> conflict-free LDS.128

template <int EPI>
__global__ void __launch_bounds__(256, 2)
gemm_tf32(const float* __restrict__ A, const float* __restrict__ W,
          const float* __restrict__ bias, const float* __restrict__ res,
          float* __restrict__ C, int M, int N, int K) {
    __shared__ uint32_t As[2][BK][GP];
    __shared__ uint32_t Bs[2][BK][GP];

    int tid = threadIdx.x;
    int bm = blockIdx.y, bn = blockIdx.x;
    int warp = tid >> 5, lane = tid & 31;
    int wm = warp & 1;    // 2 warps along M  -> 64 rows each
    int wn = warp >> 1;   // 4 warps along N  -> 32 cols each
    int mrow = lane >> 2;
    int kq = lane & 3;

    const int m0 = bm * BM, n0 = bn * BN;

    float acc[4][4][4];
#pragma unroll
    for (int i = 0; i < 4; i++)
#pragma unroll
        for (int j = 0; j < 4; j++)
#pragma unroll
            for (int k = 0; k < 4; k++) acc[i][j][k] = 0.f;

    float4 va[2], vb[2];

    // ---- staging load (LDG -> regs) ----
    auto load_stage = [&](int k0) {
#pragma unroll
        for (int i = 0; i < 2; i++) {
            int idx = tid + i * 256;
            int ra = idx >> 2, ca = (idx & 3) * 4;
            va[i] = *reinterpret_cast<const float4*>(A + (size_t)(m0 + ra) * K + k0 + ca);
            int rb = idx >> 5, cb = (idx & 31) * 4;
            vb[i] = *reinterpret_cast<const float4*>(W + (size_t)(k0 + rb) * N + n0 + cb);
        }
    };
    // ---- regs -> smem (with tf32 cvt + swizzle) ----
    auto store_stage = [&](int s) {
#pragma unroll
        for (int i = 0; i < 2; i++) {
            int idx = tid + i * 256;
            int ra = idx >> 2, ca = (idx & 3) * 4;
            int mp = (ra & 7) * 16 + (ra >> 3);
            As[s][ca + 0][mp] = f2tf(va[i].x);
            As[s][ca + 1][mp] = f2tf(va[i].y);
            As[s][ca + 2][mp] = f2tf(va[i].z);
            As[s][ca + 3][mp] = f2tf(va[i].w);
            int rb = idx >> 5, cb = (idx & 31) * 4;
            float vv[4] = {vb[i].x, vb[i].y, vb[i].z, vb[i].w};
#pragma unroll
            for (int j = 0; j < 4; j++) {
                int n = cb + j;
                Bs[s][rb][(n & 7) * 16 + (n >> 3)] = f2tf(vv[j]);
            }
        }
    };
    // ---- compute one BK tile from smem ----
    auto compute = [&](int s) {
#pragma unroll
        for (int ks = 0; ks < BK; ks += 8) {
            int kr = ks + kq;
            uint4 av0a = *reinterpret_cast<uint4*>(&As[s][kr][mrow * 16 + wm * 8]);
            uint4 av0b = *reinterpret_cast<uint4*>(&As[s][kr][mrow * 16 + wm * 8 + 4]);
            uint4 av1a = *reinterpret_cast<uint4*>(&As[s][kr + 4][mrow * 16 + wm * 8]);
            uint4 av1b = *reinterpret_cast<uint4*>(&As[s][kr + 4][mrow * 16 + wm * 8 + 4]);
            uint4 bv0 = *reinterpret_cast<uint4*>(&Bs[s][kr][mrow * 16 + wn * 4]);
            uint4 bv1 = *reinterpret_cast<uint4*>(&Bs[s][kr + 4][mrow * 16 + wn * 4]);
            uint32_t a0[8] = {av0a.x, av0a.y, av0a.z, av0a.w, av0b.x, av0b.y, av0b.z, av0b.w};
            uint32_t a1[8] = {av1a.x, av1a.y, av1a.z, av1a.w, av1b.x, av1b.y, av1b.z, av1b.w};
            uint32_t bb0[4] = {bv0.x, bv0.y, bv0.z, bv0.w};
            uint32_t bb1[4] = {bv1.x, bv1.y, bv1.z, bv1.w};
#pragma unroll
            for (int fm = 0; fm < 4; fm++) {
                uint32_t a[4] = {a0[2 * fm], a0[2 * fm + 1], a1[2 * fm], a1[2 * fm + 1]};
#pragma unroll
                for (int fn = 0; fn < 4; fn++) {
                    uint32_t b[2] = {bb0[fn], bb1[fn]};
                    mma_tf32(acc[fm][fn], a, b, acc[fm][fn]);
                }
            }
        }
    };

    load_stage(0);
    store_stage(0);
    __syncthreads();
    int buf = 0;
    for (int k0 = 0; k0 < K; k0 += BK) {
        bool more = (k0 + BK) < K;
        if (more) load_stage(k0 + BK);
        compute(buf);
        if (more) store_stage(buf ^ 1);
        __syncthreads();
        buf ^= 1;
    }

    // Epilogue
#pragma unroll
    for (int fm = 0; fm < 4; fm++) {
#pragma unroll
        for (int fn = 0; fn < 4; fn++) {
            int mr = m0 + wm * 64 + fm * 16 + mrow;
            int nc = n0 + wn * 32 + fn * 8 + (kq << 1);
            float bx = bias[nc], by = bias[nc + 1];
            float v0 = acc[fm][fn][0] + bx;
            float v1 = acc[fm][fn][1] + by;
            float v2 = acc[fm][fn][2] + bx;
            float v3 = acc[fm][fn][3] + by;
            if (EPI == 1) {
                v0 += res[(size_t)mr * N + nc];
                v1 += res[(size_t)mr * N + nc + 1];
                v2 += res[(size_t)(mr + 8) * N + nc];
                v3 += res[(size_t)(mr + 8) * N + nc + 1];
            } else if (EPI == 2) {
                v0 = gelu_exact(v0); v1 = gelu_exact(v1);
                v2 = gelu_exact(v2); v3 = gelu_exact(v3);
            }
            *reinterpret_cast<float2*>(C + (size_t)mr * N + nc) = make_float2(v0, v1);
            *reinterpret_cast<float2*>(C + (size_t)(mr + 8) * N + nc) = make_float2(v2, v3);
        }
    }
}

// ---------------------------------------------------------------------------
// Flash attention over parity streams.
// Stream (b,h,p): tokens t=0..1023 map to seq l = 2t+p. Query t attends keys
// t-j, j=0..min(256,t). Block = 4 warps, 64 stream-queries, key tiles of 32.
// All matmuls via tf32 m16n8k8 mma. Warp w owns rows 16w..16w+15 end-to-end.
// ---------------------------------------------------------------------------
#define QP 68   // Qs pitch (64+4)
#define KP 40   // Ks pitch (32+8) -> conflict-free b-loads
#define VP 68   // Vs pitch
#define PP 18   // Ps pitch (16+2)

__global__ void __launch_bounds__(128, 4)
attn_flash(const float* __restrict__ qkv, float* __restrict__ out) {
    __shared__ uint32_t Qs[64][QP];      // [d][r']  r' = (r&7)*8  + (r>>3)
    __shared__ uint32_t Ks[64][KP];      // [d][c']  c' = (c&7)*4  + (c>>3)
    __shared__ uint32_t Vs[32][VP];      // [c][d']  d' = (d&7)*8  + (d>>3)
    __shared__ uint32_t Ps[4][32][PP];   // per-warp [c][r''] r'' = m*2+e (m=0..7,e=0..1)

    int tid = threadIdx.x;
    int w = tid >> 5, lane = tid & 31;
    int mrow = lane >> 2;
    int kq = lane & 3;

    int qt0 = blockIdx.x * 64;
    int y = blockIdx.y;
    int p = y & 1, h = (y >> 1) & 15, b = y >> 5;

    // ---- load Q tile (scale folded) ----
    {
        int r = tid >> 1;
        int d0 = (tid & 1) * 32;
        int l = 2 * (qt0 + r) + p;
        const float* src = qkv + ((size_t)(b * LL + l)) * (3 * DDIM) + h * HDIM + d0;
        int rp = (r & 7) * 8 + (r >> 3);
#pragma unroll
        for (int i = 0; i < 8; i++) {
            float4 v = *reinterpret_cast<const float4*>(src + i * 4);
            int d = d0 + i * 4;
            Qs[d + 0][rp] = f2tf(v.x * 0.125f);
            Qs[d + 1][rp] = f2tf(v.y * 0.125f);
            Qs[d + 2][rp] = f2tf(v.z * 0.125f);
            Qs[d + 3][rp] = f2tf(v.w * 0.125f);
        }
    }

    float m_lo = -1e30f, m_hi = -1e30f, l_lo = 0.f, l_hi = 0.f;
    float o[8][4];
#pragma unroll
    for (int i = 0; i < 8; i++)
#pragma unroll
        for (int j = 0; j < 4; j++) o[i][j] = 0.f;

    int tq_lo = qt0 + 16 * w + mrow;
    int tq_hi = tq_lo + 8;

    int ktbeg = qt0 - 256; if (ktbeg < 0) ktbeg = 0;
    for (int kt0 = ktbeg; kt0 <= qt0 + 32; kt0 += 32) {
        // ---- load K,V tiles ----
        {
            int c = tid >> 2;
            int d0 = (tid & 3) * 16;
            int lk = 2 * (kt0 + c) + p;
            const float* kb = qkv + ((size_t)(b * LL + lk)) * (3 * DDIM) + DDIM + h * HDIM + d0;
            const float* vb = kb + DDIM;
            int cp = (c & 7) * 4 + (c >> 3);
#pragma unroll
            for (int i = 0; i < 4; i++) {
                float4 kv = *reinterpret_cast<const float4*>(kb + i * 4);
                int d = d0 + i * 4;
                Ks[d + 0][cp] = f2tf(kv.x);
                Ks[d + 1][cp] = f2tf(kv.y);
                Ks[d + 2][cp] = f2tf(kv.z);
                Ks[d + 3][cp] = f2tf(kv.w);
                float4 vv = *reinterpret_cast<const float4*>(vb + i * 4);
                Vs[c][((d + 0) & 7) * 8 + ((d + 0) >> 3)] = f2tf(vv.x);
                Vs[c][((d + 1) & 7) * 8 + ((d + 1) >> 3)] = f2tf(vv.y);
                Vs[c][((d + 2) & 7) * 8 + ((d + 2) >> 3)] = f2tf(vv.z);
                Vs[c][((d + 3) & 7) * 8 + ((d + 3) >> 3)] = f2tf(vv.w);
            }
        }
        __syncthreads();

        // ---- S = Q K^T (16x32 per warp) ----
        float s_acc[4][4];
#pragma unroll
        for (int fn = 0; fn < 4; fn++)
#pragma unroll
            for (int j = 0; j < 4; j++) s_acc[fn][j] = 0.f;
#pragma unroll
        for (int ks = 0; ks < 64; ks += 8) {
            int kr = ks + kq;
            uint2 alo = *reinterpret_cast<uint2*>(&Qs[kr][mrow * 8 + 2 * w]);
            uint2 ahi = *reinterpret_cast<uint2*>(&Qs[kr + 4][mrow * 8 + 2 * w]);
            uint32_t a[4] = {alo.x, alo.y, ahi.x, ahi.y};
            uint4 b0 = *reinterpret_cast<uint4*>(&Ks[kr][mrow * 4]);
            uint4 b1 = *reinterpret_cast<uint4*>(&Ks[kr + 4][mrow * 4]);
            uint32_t bb0[4] = {b0.x, b0.y, b0.z, b0.w};
            uint32_t bb1[4] = {b1.x, b1.y, b1.z, b1.w};
#pragma unroll
            for (int fn = 0; fn < 4; fn++) {
                uint32_t bf[2] = {bb0[fn], bb1[fn]};
                mma_tf32(s_acc[fn], a, bf, s_acc[fn]);
            }
        }

        // ---- mask + online softmax ----
        float mt_lo = -1e30f, mt_hi = -1e30f;
#pragma unroll
        for (int fn = 0; fn < 4; fn++) {
#pragma unroll
            for (int j = 0; j < 2; j++) {
                int tk = kt0 + 8 * fn + 2 * kq + j;
                if (!(tk <= tq_lo && tq_lo - tk <= 256)) s_acc[fn][j] = -1e30f;
                if (!(tk <= tq_hi && tq_hi - tk <= 256)) s_acc[fn][2 + j] = -1e30f;
                mt_lo = fmaxf(mt_lo, s_acc[fn][j]);
                mt_hi = fmaxf(mt_hi, s_acc[fn][2 + j]);
            }
        }
        mt_lo = fmaxf(mt_lo, __shfl_xor_sync(~0u, mt_lo, 1));
        mt_lo = fmaxf(mt_lo, __shfl_xor_sync(~0u, mt_lo, 2));
        mt_hi = fmaxf(mt_hi, __shfl_xor_sync(~0u, mt_hi, 1));
        mt_hi = fmaxf(mt_hi, __shfl_xor_sync(~0u, mt_hi, 2));
        float mn_lo = fmaxf(m_lo, mt_lo);
        float mn_hi = fmaxf(m_hi, mt_hi);
        float cf_lo = __expf(m_lo - mn_lo);
        float cf_hi = __expf(m_hi - mn_hi);
        m_lo = mn_lo; m_hi = mn_hi;

        float rs_lo = 0.f, rs_hi = 0.f;
        int rpp = mrow * 2;
#pragma unroll
        for (int fn = 0; fn < 4; fn++) {
#pragma unroll
            for (int j = 0; j < 2; j++) {
                float plo = __expf(s_acc[fn][j] - mn_lo);
                if (s_acc[fn][j] < -1e29f) plo = 0.f;
                float phi = __expf(s_acc[fn][2 + j] - mn_hi);
                if (s_acc[fn][2 + j] < -1e29f) phi = 0.f;
                rs_lo += plo; rs_hi += phi;
                int c = 8 * fn + 2 * kq + j;
                Ps[w][c][rpp] = f2tf(plo);
                Ps[w][c][rpp + 1] = f2tf(phi);
            }
        }
        rs_lo += __shfl_xor_sync(~0u, rs_lo, 1);
        rs_lo += __shfl_xor_sync(~0u, rs_lo, 2);
        rs_hi += __shfl_xor_sync(~0u, rs_hi, 1);
        rs_hi += __shfl_xor_sync(~0u, rs_hi, 2);
        l_lo = l_lo * cf_lo + rs_lo;
        l_hi = l_hi * cf_hi + rs_hi;
#pragma unroll
        for (int fd = 0; fd < 8; fd++) {
            o[fd][0] *= cf_lo; o[fd][1] *= cf_lo;
            o[fd][2] *= cf_hi; o[fd][3] *= cf_hi;
        }
        __syncwarp();

        // ---- O += P V (16x64 per warp, k = 32) ----
#pragma unroll
        for (int ks = 0; ks < 32; ks += 8) {
            int kr = ks + kq;
            uint2 alo = *reinterpret_cast<uint2*>(&Ps[w][kr][mrow * 2]);
            uint2 ahi = *reinterpret_cast<uint2*>(&Ps[w][kr + 4][mrow * 2]);
            uint32_t a[4] = {alo.x, alo.y, ahi.x, ahi.y};
            uint4 b00 = *reinterpret_cast<uint4*>(&Vs[kr][mrow * 8]);
            uint4 b01 = *reinterpret_cast<uint4*>(&Vs[kr][mrow * 8 + 4]);
            uint4 b10 = *reinterpret_cast<uint4*>(&Vs[kr + 4][mrow * 8]);
            uint4 b11 = *reinterpret_cast<uint4*>(&Vs[kr + 4][mrow * 8 + 4]);
            uint32_t v0[8] = {b00.x, b00.y, b00.z, b00.w, b01.x, b01.y, b01.z, b01.w};
            uint32_t v1[8] = {b10.x, b10.y, b10.z, b10.w, b11.x, b11.y, b11.z, b11.w};
#pragma unroll
            for (int fd = 0; fd < 8; fd++) {
                uint32_t bf[2] = {v0[fd], v1[fd]};
                mma_tf32(o[fd], a, bf, o[fd]);
            }
        }
        __syncthreads();
    }

    // ---- epilogue ----
    float inv_lo = 1.0f / l_lo;
    float inv_hi = 1.0f / l_hi;
    int llo = 2 * tq_lo + p;
    int lhi = 2 * tq_hi + p;
    float* obl = out + ((size_t)(b * LL + llo)) * DDIM + h * HDIM;
    float* obh = out + ((size_t)(b * LL + lhi)) * DDIM + h * HDIM;
#pragma unroll
    for (int fd = 0; fd < 8; fd++) {
        int d = 8 * fd + 2 * kq;
        *reinterpret_cast<float2*>(obl + d) = make_float2(o[fd][0] * inv_lo, o[fd][1] * inv_lo);
        *reinterpret_cast<float2*>(obh + d) = make_float2(o[fd][2] * inv_hi, o[fd][3] * inv_hi);
    }
}

// ---------------------------------------------------------------------------
// Launch
// ---------------------------------------------------------------------------
extern "C" void kernel_launch(void* const* d_in, const int* in_sizes, int n_in,
                              void* d_out, int out_size) {
    const float* x     = (const float*)d_in[0];
    const float* ln1_g = (const float*)d_in[1];
    const float* ln1_b = (const float*)d_in[2];
    const float* Wqkv  = (const float*)d_in[3];
    const float* bqkv  = (const float*)d_in[4];
    const float* Wout  = (const float*)d_in[5];
    const float* bout  = (const float*)d_in[6];
    const float* ln2_g = (const float*)d_in[7];
    const float* ln2_b = (const float*)d_in[8];
    const float* W1    = (const float*)d_in[9];
    const float* b1    = (const float*)d_in[10];
    const float* W2    = (const float*)d_in[11];
    const float* b2    = (const float*)d_in[12];
    float* out = (float*)d_out;

    float *h, *qkv, *attn, *x1, *f;
    cudaGetSymbolAddress((void**)&h, g_h);
    cudaGetSymbolAddress((void**)&qkv, g_qkv);
    cudaGetSymbolAddress((void**)&attn, g_attn);
    cudaGetSymbolAddress((void**)&x1, g_x1);
    cudaGetSymbolAddress((void**)&f, g_f);

    // 1. LN1
    ln_kernel<<<MM, 256>>>(x, ln1_g, ln1_b, h);
    // 2. QKV = h @ Wqkv + bqkv          [4096,1024]x[1024,3072]
    gemm_tf32<0><<<dim3(3 * DDIM / BN, MM / BM), 256>>>(h, Wqkv, bqkv, nullptr,
                                                        qkv, MM, 3 * DDIM, DDIM);
    // 3. attention (flash, parity streams)
    attn_flash<<<dim3(16, 64), 128>>>(qkv, attn);
    // 4. x1 = x + attn @ Wout + bout    [4096,1024]x[1024,1024]
    gemm_tf32<1><<<dim3(DDIM / BN, MM / BM), 256>>>(attn, Wout, bout, x,
                                                    x1, MM, DDIM, DDIM);
    // 5. LN2
    ln_kernel<<<MM, 256>>>(x1, ln2_g, ln2_b, h);
    // 6. f = gelu(h @ W1 + b1)          [4096,1024]x[1024,4096]
    gemm_tf32<2><<<dim3(4 * DDIM / BN, MM / BM), 256>>>(h, W1, b1, nullptr,
                                                        f, MM, 4 * DDIM, DDIM);
    // 7. out = x1 + f @ W2 + b2         [4096,4096]x[4096,1024]
    gemm_tf32<1><<<dim3(DDIM / BN, MM / BM), 256>>>(f, W2, b2, x1,
                                                    out, MM, DDIM, 4 * DDIM);
}

// round 3
// speedup vs baseline: 1.9970x; 1.8230x over previous
#include <cuda_runtime.h>
#include <cstdint>
#include <math.h>

// Problem constants
#define BB 2
#define LL 2048
#define DDIM 1024
#define HH 16
#define HDIM 64
#define MM (BB*LL)          // 4096 rows
#define WIN 512
#define DIL 2

// Scratch (device globals; no allocation allowed)
__device__ float g_h[(size_t)MM*DDIM];          // LN output (reused for LN2)
__device__ float g_qkv[(size_t)MM*3*DDIM];      // QKV
__device__ float g_attn[(size_t)MM*DDIM];       // attention output (B,L,D)
__device__ float g_x1[(size_t)MM*DDIM];         // x + attn_out @ Wout
__device__ float g_f[(size_t)MM*4*DDIM];        // FFN hidden

__device__ __forceinline__ uint32_t f2tf(float x) {
    uint32_t r;
    asm("cvt.rna.tf32.f32 %0, %1;" : "=r"(r) : "f"(x));
    return r;
}

__device__ __forceinline__ void mma_tf32(float d[4], const uint32_t a[4],
                                         const uint32_t b[2], const float c[4]) {
    asm volatile(
        "mma.sync.aligned.m16n8k8.row.col.f32.tf32.tf32.f32 "
        "{%0,%1,%2,%3}, {%4,%5,%6,%7}, {%8,%9}, {%10,%11,%12,%13};\n"
        : "=f"(d[0]), "=f"(d[1]), "=f"(d[2]), "=f"(d[3])
        : "r"(a[0]), "r"(a[1]), "r"(a[2]), "r"(a[3]),
          "r"(b[0]), "r"(b[1]),
          "f"(c[0]), "f"(c[1]), "f"(c[2]), "f"(c[3]));
}

__device__ __forceinline__ float gelu_exact(float x) {
    return 0.5f * x * (1.0f + erff(x * 0.70710678118654752f));
}

__device__ __forceinline__ void cp_async16(uint32_t smem_addr, const void* gptr) {
    asm volatile("cp.async.cg.shared.global [%0], [%1], 16;\n"
                 :: "r"(smem_addr), "l"(gptr));
}
__device__ __forceinline__ void cp_commit() {
    asm volatile("cp.async.commit_group;\n");
}
__device__ __forceinline__ void cp_wait0() {
    asm volatile("cp.async.wait_group 0;\n");
}

// ---------------------------------------------------------------------------
// LayerNorm: one block (256 threads) per row of 1024 floats
// ---------------------------------------------------------------------------
__global__ void ln_kernel(const float* __restrict__ x, const float* __restrict__ g,
                          const float* __restrict__ b, float* __restrict__ out) {
    int row = blockIdx.x;
    int t = threadIdx.x;
    const float4 xv = reinterpret_cast<const float4*>(x + (size_t)row * DDIM)[t];

    __shared__ float warp_s[8], warp_q[8];
    __shared__ float s_mu, s_r;

    float s = xv.x + xv.y + xv.z + xv.w;
    float q = xv.x*xv.x + xv.y*xv.y + xv.z*xv.z + xv.w*xv.w;
#pragma unroll
    for (int o = 16; o; o >>= 1) {
        s += __shfl_xor_sync(~0u, s, o);
        q += __shfl_xor_sync(~0u, q, o);
    }
    if ((t & 31) == 0) { warp_s[t >> 5] = s; warp_q[t >> 5] = q; }
    __syncthreads();
    if (t == 0) {
        float S = 0.f, Q = 0.f;
#pragma unroll
        for (int i = 0; i < 8; i++) { S += warp_s[i]; Q += warp_q[i]; }
        float mu = S * (1.0f / DDIM);
        float var = Q * (1.0f / DDIM) - mu * mu;
        s_mu = mu;
        s_r = rsqrtf(var + 1e-5f);
    }
    __syncthreads();
    float mu = s_mu, r = s_r;
    float4 gv = reinterpret_cast<const float4*>(g)[t];
    float4 bv = reinterpret_cast<const float4*>(b)[t];
    float4 o;
    o.x = (xv.x - mu) * r * gv.x + bv.x;
    o.y = (xv.y - mu) * r * gv.y + bv.y;
    o.z = (xv.z - mu) * r * gv.z + bv.z;
    o.w = (xv.w - mu) * r * gv.w + bv.w;
    reinterpret_cast<float4*>(out + (size_t)row * DDIM)[t] = o;
}

// ---------------------------------------------------------------------------
// TF32 GEMM v3: cp.async double-buffered, conflict-free-by-pitch smem layouts.
// C[M,N] = A[M,K] @ W[K,N] + bias; EPI: 0=bias, 1=bias+residual, 2=bias+GELU
// Block 128x128x16, 256 threads, warp tile 64x32 via m16n8k8 tf32 mma.
// Raw fp32 bits fed to tf32 MMA (hw truncation).
// As[m][k]: pitch AP=20 words -> a-frag banks (mrow*20+kq)%32 all distinct.
// Bs[k][n]: pitch BP=136 words -> b-frag banks (kq*136+mrow)%32 all distinct.
// ---------------------------------------------------------------------------
#define BM 128
#define BN 128
#define BK 16
#define AP 20
#define BP 136

template <int EPI>
__global__ void __launch_bounds__(256)
gemm_tf32(const float* __restrict__ A, const float* __restrict__ W,
          const float* __restrict__ bias, const float* __restrict__ res,
          float* __restrict__ C, int M, int N, int K) {
    __shared__ float As[2][BM][AP];
    __shared__ float Bs[2][BK][BP];

    int tid = threadIdx.x;
    int bm = blockIdx.y, bn = blockIdx.x;
    int warp = tid >> 5, lane = tid & 31;
    int wm = warp & 1;    // 2 warps along M  -> 64 rows each
    int wn = warp >> 1;   // 4 warps along N  -> 32 cols each
    int mrow = lane >> 2;
    int kq = lane & 3;

    const int m0 = bm * BM, n0 = bn * BN;

    // per-thread cp.async source/dest (2 chunks of A, 2 of B per stage)
    int ar0 = tid >> 2, ac0 = (tid & 3) * 4;            // A chunk 0: row, col
    int ar1 = (tid + 256) >> 2, ac1 = ac0;              // A chunk 1
    int br0 = tid >> 5, bc0 = (tid & 31) * 4;           // B chunk 0
    int br1 = (tid + 256) >> 5, bc1 = bc0;              // B chunk 1
    const float* agp0 = A + (size_t)(m0 + ar0) * K + ac0;
    const float* agp1 = A + (size_t)(m0 + ar1) * K + ac1;
    const float* bgp0 = W + (size_t)br0 * N + n0 + bc0;
    const float* bgp1 = W + (size_t)br1 * N + n0 + bc1;
    uint32_t asm0 = (uint32_t)__cvta_generic_to_shared(&As[0][ar0][ac0]);
    uint32_t asm1 = (uint32_t)__cvta_generic_to_shared(&As[0][ar1][ac1]);
    uint32_t bsm0 = (uint32_t)__cvta_generic_to_shared(&Bs[0][br0][bc0]);
    uint32_t bsm1 = (uint32_t)__cvta_generic_to_shared(&Bs[0][br1][bc1]);
    const uint32_t aStage = BM * AP * 4;   // bytes per A stage
    const uint32_t bStage = BK * BP * 4;   // bytes per B stage

    float acc[4][4][4];
#pragma unroll
    for (int i = 0; i < 4; i++)
#pragma unroll
        for (int j = 0; j < 4; j++)
#pragma unroll
            for (int k = 0; k < 4; k++) acc[i][j][k] = 0.f;

    auto issue_loads = [&](int k0, int s) {
        cp_async16(asm0 + s * aStage, agp0 + k0);
        cp_async16(asm1 + s * aStage, agp1 + k0);
        cp_async16(bsm0 + s * bStage, bgp0 + (size_t)k0 * N);
        cp_async16(bsm1 + s * bStage, bgp1 + (size_t)k0 * N);
        cp_commit();
    };

    issue_loads(0, 0);
    int nk = K / BK;
    for (int it = 0; it < nk; it++) {
        cp_wait0();
        __syncthreads();
        if (it + 1 < nk) issue_loads((it + 1) * BK, (it + 1) & 1);
        int s = it & 1;
        const float (*as)[AP] = As[s];
        const float (*bs)[BP] = Bs[s];
#pragma unroll
        for (int ks = 0; ks < BK; ks += 8) {
            int kr = ks + kq;
            uint32_t a[4][4], b[4][2];
#pragma unroll
            for (int fm = 0; fm < 4; fm++) {
                int mb = wm * 64 + fm * 16 + mrow;
                a[fm][0] = __float_as_uint(as[mb][kr]);
                a[fm][1] = __float_as_uint(as[mb + 8][kr]);
                a[fm][2] = __float_as_uint(as[mb][kr + 4]);
                a[fm][3] = __float_as_uint(as[mb + 8][kr + 4]);
            }
            int nb = wn * 32 + mrow;
#pragma unroll
            for (int fn = 0; fn < 4; fn++) {
                b[fn][0] = __float_as_uint(bs[kr][nb + fn * 8]);
                b[fn][1] = __float_as_uint(bs[kr + 4][nb + fn * 8]);
            }
#pragma unroll
            for (int fm = 0; fm < 4; fm++)
#pragma unroll
                for (int fn = 0; fn < 4; fn++)
                    mma_tf32(acc[fm][fn], a[fm], b[fn], acc[fm][fn]);
        }
        __syncthreads();
    }

    // Epilogue
#pragma unroll
    for (int fm = 0; fm < 4; fm++) {
#pragma unroll
        for (int fn = 0; fn < 4; fn++) {
            int mr = m0 + wm * 64 + fm * 16 + mrow;
            int nc = n0 + wn * 32 + fn * 8 + (kq << 1);
            float bx = bias[nc], by = bias[nc + 1];
            float v0 = acc[fm][fn][0] + bx;
            float v1 = acc[fm][fn][1] + by;
            float v2 = acc[fm][fn][2] + bx;
            float v3 = acc[fm][fn][3] + by;
            if (EPI == 1) {
                v0 += res[(size_t)mr * N + nc];
                v1 += res[(size_t)mr * N + nc + 1];
                v2 += res[(size_t)(mr + 8) * N + nc];
                v3 += res[(size_t)(mr + 8) * N + nc + 1];
            } else if (EPI == 2) {
                v0 = gelu_exact(v0); v1 = gelu_exact(v1);
                v2 = gelu_exact(v2); v3 = gelu_exact(v3);
            }
            *reinterpret_cast<float2*>(C + (size_t)mr * N + nc) = make_float2(v0, v1);
            *reinterpret_cast<float2*>(C + (size_t)(mr + 8) * N + nc) = make_float2(v2, v3);
        }
    }
}

// ---------------------------------------------------------------------------
// Flash attention over parity streams. (unchanged from round 2)
// ---------------------------------------------------------------------------
#define QP 68
#define KP 40
#define VP 68
#define PP 18

__global__ void __launch_bounds__(128, 4)
attn_flash(const float* __restrict__ qkv, float* __restrict__ out) {
    __shared__ uint32_t Qs[64][QP];
    __shared__ uint32_t Ks[64][KP];
    __shared__ uint32_t Vs[32][VP];
    __shared__ uint32_t Ps[4][32][PP];

    int tid = threadIdx.x;
    int w = tid >> 5, lane = tid & 31;
    int mrow = lane >> 2;
    int kq = lane & 3;

    int qt0 = blockIdx.x * 64;
    int y = blockIdx.y;
    int p = y & 1, h = (y >> 1) & 15, b = y >> 5;

    {
        int r = tid >> 1;
        int d0 = (tid & 1) * 32;
        int l = 2 * (qt0 + r) + p;
        const float* src = qkv + ((size_t)(b * LL + l)) * (3 * DDIM) + h * HDIM + d0;
        int rp = (r & 7) * 8 + (r >> 3);
#pragma unroll
        for (int i = 0; i < 8; i++) {
            float4 v = *reinterpret_cast<const float4*>(src + i * 4);
            int d = d0 + i * 4;
            Qs[d + 0][rp] = f2tf(v.x * 0.125f);
            Qs[d + 1][rp] = f2tf(v.y * 0.125f);
            Qs[d + 2][rp] = f2tf(v.z * 0.125f);
            Qs[d + 3][rp] = f2tf(v.w * 0.125f);
        }
    }

    float m_lo = -1e30f, m_hi = -1e30f, l_lo = 0.f, l_hi = 0.f;
    float o[8][4];
#pragma unroll
    for (int i = 0; i < 8; i++)
#pragma unroll
        for (int j = 0; j < 4; j++) o[i][j] = 0.f;

    int tq_lo = qt0 + 16 * w + mrow;
    int tq_hi = tq_lo + 8;

    int ktbeg = qt0 - 256; if (ktbeg < 0) ktbeg = 0;
    for (int kt0 = ktbeg; kt0 <= qt0 + 32; kt0 += 32) {
        {
            int c = tid >> 2;
            int d0 = (tid & 3) * 16;
            int lk = 2 * (kt0 + c) + p;
            const float* kb = qkv + ((size_t)(b * LL + lk)) * (3 * DDIM) + DDIM + h * HDIM + d0;
            const float* vb = kb + DDIM;
            int cp = (c & 7) * 4 + (c >> 3);
#pragma unroll
            for (int i = 0; i < 4; i++) {
                float4 kv = *reinterpret_cast<const float4*>(kb + i * 4);
                int d = d0 + i * 4;
                Ks[d + 0][cp] = f2tf(kv.x);
                Ks[d + 1][cp] = f2tf(kv.y);
                Ks[d + 2][cp] = f2tf(kv.z);
                Ks[d + 3][cp] = f2tf(kv.w);
                float4 vv = *reinterpret_cast<const float4*>(vb + i * 4);
                Vs[c][((d + 0) & 7) * 8 + ((d + 0) >> 3)] = f2tf(vv.x);
                Vs[c][((d + 1) & 7) * 8 + ((d + 1) >> 3)] = f2tf(vv.y);
                Vs[c][((d + 2) & 7) * 8 + ((d + 2) >> 3)] = f2tf(vv.z);
                Vs[c][((d + 3) & 7) * 8 + ((d + 3) >> 3)] = f2tf(vv.w);
            }
        }
        __syncthreads();

        float s_acc[4][4];
#pragma unroll
        for (int fn = 0; fn < 4; fn++)
#pragma unroll
            for (int j = 0; j < 4; j++) s_acc[fn][j] = 0.f;
#pragma unroll
        for (int ks = 0; ks < 64; ks += 8) {
            int kr = ks + kq;
            uint2 alo = *reinterpret_cast<uint2*>(&Qs[kr][mrow * 8 + 2 * w]);
            uint2 ahi = *reinterpret_cast<uint2*>(&Qs[kr + 4][mrow * 8 + 2 * w]);
            uint32_t a[4] = {alo.x, alo.y, ahi.x, ahi.y};
            uint4 b0 = *reinterpret_cast<uint4*>(&Ks[kr][mrow * 4]);
            uint4 b1 = *reinterpret_cast<uint4*>(&Ks[kr + 4][mrow * 4]);
            uint32_t bb0[4] = {b0.x, b0.y, b0.z, b0.w};
            uint32_t bb1[4] = {b1.x, b1.y, b1.z, b1.w};
#pragma unroll
            for (int fn = 0; fn < 4; fn++) {
                uint32_t bf[2] = {bb0[fn], bb1[fn]};
                mma_tf32(s_acc[fn], a, bf, s_acc[fn]);
            }
        }

        float mt_lo = -1e30f, mt_hi = -1e30f;
#pragma unroll
        for (int fn = 0; fn < 4; fn++) {
#pragma unroll
            for (int j = 0; j < 2; j++) {
                int tk = kt0 + 8 * fn + 2 * kq + j;
                if (!(tk <= tq_lo && tq_lo - tk <= 256)) s_acc[fn][j] = -1e30f;
                if (!(tk <= tq_hi && tq_hi - tk <= 256)) s_acc[fn][2 + j] = -1e30f;
                mt_lo = fmaxf(mt_lo, s_acc[fn][j]);
                mt_hi = fmaxf(mt_hi, s_acc[fn][2 + j]);
            }
        }
        mt_lo = fmaxf(mt_lo, __shfl_xor_sync(~0u, mt_lo, 1));
        mt_lo = fmaxf(mt_lo, __shfl_xor_sync(~0u, mt_lo, 2));
        mt_hi = fmaxf(mt_hi, __shfl_xor_sync(~0u, mt_hi, 1));
        mt_hi = fmaxf(mt_hi, __shfl_xor_sync(~0u, mt_hi, 2));
        float mn_lo = fmaxf(m_lo, mt_lo);
        float mn_hi = fmaxf(m_hi, mt_hi);
        float cf_lo = __expf(m_lo - mn_lo);
        float cf_hi = __expf(m_hi - mn_hi);
        m_lo = mn_lo; m_hi = mn_hi;

        float rs_lo = 0.f, rs_hi = 0.f;
        int rpp = mrow * 2;
#pragma unroll
        for (int fn = 0; fn < 4; fn++) {
#pragma unroll
            for (int j = 0; j < 2; j++) {
                float plo = __expf(s_acc[fn][j] - mn_lo);
                if (s_acc[fn][j] < -1e29f) plo = 0.f;
                float phi = __expf(s_acc[fn][2 + j] - mn_hi);
                if (s_acc[fn][2 + j] < -1e29f) phi = 0.f;
                rs_lo += plo; rs_hi += phi;
                int c = 8 * fn + 2 * kq + j;
                Ps[w][c][rpp] = f2tf(plo);
                Ps[w][c][rpp + 1] = f2tf(phi);
            }
        }
        rs_lo += __shfl_xor_sync(~0u, rs_lo, 1);
        rs_lo += __shfl_xor_sync(~0u, rs_lo, 2);
        rs_hi += __shfl_xor_sync(~0u, rs_hi, 1);
        rs_hi += __shfl_xor_sync(~0u, rs_hi, 2);
        l_lo = l_lo * cf_lo + rs_lo;
        l_hi = l_hi * cf_hi + rs_hi;
#pragma unroll
        for (int fd = 0; fd < 8; fd++) {
            o[fd][0] *= cf_lo; o[fd][1] *= cf_lo;
            o[fd][2] *= cf_hi; o[fd][3] *= cf_hi;
        }
        __syncwarp();

#pragma unroll
        for (int ks = 0; ks < 32; ks += 8) {
            int kr = ks + kq;
            uint2 alo = *reinterpret_cast<uint2*>(&Ps[w][kr][mrow * 2]);
            uint2 ahi = *reinterpret_cast<uint2*>(&Ps[w][kr + 4][mrow * 2]);
            uint32_t a[4] = {alo.x, alo.y, ahi.x, ahi.y};
            uint4 b00 = *reinterpret_cast<uint4*>(&Vs[kr][mrow * 8]);
            uint4 b01 = *reinterpret_cast<uint4*>(&Vs[kr][mrow * 8 + 4]);
            uint4 b10 = *reinterpret_cast<uint4*>(&Vs[kr + 4][mrow * 8]);
            uint4 b11 = *reinterpret_cast<uint4*>(&Vs[kr + 4][mrow * 8 + 4]);
            uint32_t v0[8] = {b00.x, b00.y, b00.z, b00.w, b01.x, b01.y, b01.z, b01.w};
            uint32_t v1[8] = {b10.x, b10.y, b10.z, b10.w, b11.x, b11.y, b11.z, b11.w};
#pragma unroll
            for (int fd = 0; fd < 8; fd++) {
                uint32_t bf[2] = {v0[fd], v1[fd]};
                mma_tf32(o[fd], a, bf, o[fd]);
            }
        }
        __syncthreads();
    }

    float inv_lo = 1.0f / l_lo;
    float inv_hi = 1.0f / l_hi;
    int llo = 2 * tq_lo + p;
    int lhi = 2 * tq_hi + p;
    float* obl = out + ((size_t)(b * LL + llo)) * DDIM + h * HDIM;
    float* obh = out + ((size_t)(b * LL + lhi)) * DDIM + h * HDIM;
#pragma unroll
    for (int fd = 0; fd < 8; fd++) {
        int d = 8 * fd + 2 * kq;
        *reinterpret_cast<float2*>(obl + d) = make_float2(o[fd][0] * inv_lo, o[fd][1] * inv_lo);
        *reinterpret_cast<float2*>(obh + d) = make_float2(o[fd][2] * inv_hi, o[fd][3] * inv_hi);
    }
}

// ---------------------------------------------------------------------------
// Launch
// ---------------------------------------------------------------------------
extern "C" void kernel_launch(void* const* d_in, const int* in_sizes, int n_in,
                              void* d_out, int out_size) {
    const float* x     = (const float*)d_in[0];
    const float* ln1_g = (const float*)d_in[1];
    const float* ln1_b = (const float*)d_in[2];
    const float* Wqkv  = (const float*)d_in[3];
    const float* bqkv  = (const float*)d_in[4];
    const float* Wout  = (const float*)d_in[5];
    const float* bout  = (const float*)d_in[6];
    const float* ln2_g = (const float*)d_in[7];
    const float* ln2_b = (const float*)d_in[8];
    const float* W1    = (const float*)d_in[9];
    const float* b1    = (const float*)d_in[10];
    const float* W2    = (const float*)d_in[11];
    const float* b2    = (const float*)d_in[12];
    float* out = (float*)d_out;

    float *h, *qkv, *attn, *x1, *f;
    cudaGetSymbolAddress((void**)&h, g_h);
    cudaGetSymbolAddress((void**)&qkv, g_qkv);
    cudaGetSymbolAddress((void**)&attn, g_attn);
    cudaGetSymbolAddress((void**)&x1, g_x1);
    cudaGetSymbolAddress((void**)&f, g_f);

    // 1. LN1
    ln_kernel<<<MM, 256>>>(x, ln1_g, ln1_b, h);
    // 2. QKV = h @ Wqkv + bqkv          [4096,1024]x[1024,3072]
    gemm_tf32<0><<<dim3(3 * DDIM / BN, MM / BM), 256>>>(h, Wqkv, bqkv, nullptr,
                                                        qkv, MM, 3 * DDIM, DDIM);
    // 3. attention (flash, parity streams)
    attn_flash<<<dim3(16, 64), 128>>>(qkv, attn);
    // 4. x1 = x + attn @ Wout + bout    [4096,1024]x[1024,1024]
    gemm_tf32<1><<<dim3(DDIM / BN, MM / BM), 256>>>(attn, Wout, bout, x,
                                                    x1, MM, DDIM, DDIM);
    // 5. LN2
    ln_kernel<<<MM, 256>>>(x1, ln2_g, ln2_b, h);
    // 6. f = gelu(h @ W1 + b1)          [4096,1024]x[1024,4096]
    gemm_tf32<2><<<dim3(4 * DDIM / BN, MM / BM), 256>>>(h, W1, b1, nullptr,
                                                        f, MM, 4 * DDIM, DDIM);
    // 7. out = x1 + f @ W2 + b2         [4096,4096]x[4096,1024]
    gemm_tf32<1><<<dim3(DDIM / BN, MM / BM), 256>>>(f, W2, b2, x1,
                                                    out, MM, DDIM, 4 * DDIM);
}

// round 4
// speedup vs baseline: 2.1270x; 1.0651x over previous
#include <cuda_runtime.h>
#include <cstdint>
#include <math.h>

// Problem constants
#define BB 2
#define LL 2048
#define DDIM 1024
#define HH 16
#define HDIM 64
#define MM (BB*LL)          // 4096 rows
#define WIN 512
#define DIL 2

// Scratch (device globals; no allocation allowed)
__device__ float g_h[(size_t)MM*DDIM];          // LN output (reused for LN2)
__device__ float g_qkv[(size_t)MM*3*DDIM];      // QKV
__device__ float g_attn[(size_t)MM*DDIM];       // attention output (B,L,D)
__device__ float g_x1[(size_t)MM*DDIM];         // x + attn_out @ Wout
__device__ float g_f[(size_t)MM*4*DDIM];        // FFN hidden

__device__ __forceinline__ uint32_t f2tf(float x) {
    uint32_t r;
    asm("cvt.rna.tf32.f32 %0, %1;" : "=r"(r) : "f"(x));
    return r;
}
__device__ __forceinline__ float f2tf_f(float x) {
    return __uint_as_float(f2tf(x));
}

__device__ __forceinline__ void mma_tf32(float d[4], const uint32_t a[4],
                                         const uint32_t b[2], const float c[4]) {
    asm volatile(
        "mma.sync.aligned.m16n8k8.row.col.f32.tf32.tf32.f32 "
        "{%0,%1,%2,%3}, {%4,%5,%6,%7}, {%8,%9}, {%10,%11,%12,%13};\n"
        : "=f"(d[0]), "=f"(d[1]), "=f"(d[2]), "=f"(d[3])
        : "r"(a[0]), "r"(a[1]), "r"(a[2]), "r"(a[3]),
          "r"(b[0]), "r"(b[1]),
          "f"(c[0]), "f"(c[1]), "f"(c[2]), "f"(c[3]));
}

__device__ __forceinline__ float gelu_exact(float x) {
    return 0.5f * x * (1.0f + erff(x * 0.70710678118654752f));
}

__device__ __forceinline__ void cp_async16(uint32_t smem_addr, const void* gptr) {
    asm volatile("cp.async.cg.shared.global [%0], [%1], 16;\n"
                 :: "r"(smem_addr), "l"(gptr));
}
__device__ __forceinline__ void cp_commit() {
    asm volatile("cp.async.commit_group;\n");
}
__device__ __forceinline__ void cp_wait2() {
    asm volatile("cp.async.wait_group 2;\n");
}

// ---------------------------------------------------------------------------
// LayerNorm: one block (256 threads) per row of 1024 floats.
// Output rounded to tf32 grid (RN) — it only feeds GEMM A-operands.
// ---------------------------------------------------------------------------
__global__ void ln_kernel(const float* __restrict__ x, const float* __restrict__ g,
                          const float* __restrict__ b, float* __restrict__ out) {
    int row = blockIdx.x;
    int t = threadIdx.x;
    const float4 xv = reinterpret_cast<const float4*>(x + (size_t)row * DDIM)[t];

    __shared__ float warp_s[8], warp_q[8];
    __shared__ float s_mu, s_r;

    float s = xv.x + xv.y + xv.z + xv.w;
    float q = xv.x*xv.x + xv.y*xv.y + xv.z*xv.z + xv.w*xv.w;
#pragma unroll
    for (int o = 16; o; o >>= 1) {
        s += __shfl_xor_sync(~0u, s, o);
        q += __shfl_xor_sync(~0u, q, o);
    }
    if ((t & 31) == 0) { warp_s[t >> 5] = s; warp_q[t >> 5] = q; }
    __syncthreads();
    if (t == 0) {
        float S = 0.f, Q = 0.f;
#pragma unroll
        for (int i = 0; i < 8; i++) { S += warp_s[i]; Q += warp_q[i]; }
        float mu = S * (1.0f / DDIM);
        float var = Q * (1.0f / DDIM) - mu * mu;
        s_mu = mu;
        s_r = rsqrtf(var + 1e-5f);
    }
    __syncthreads();
    float mu = s_mu, r = s_r;
    float4 gv = reinterpret_cast<const float4*>(g)[t];
    float4 bv = reinterpret_cast<const float4*>(b)[t];
    float4 o;
    o.x = f2tf_f((xv.x - mu) * r * gv.x + bv.x);
    o.y = f2tf_f((xv.y - mu) * r * gv.y + bv.y);
    o.z = f2tf_f((xv.z - mu) * r * gv.z + bv.z);
    o.w = f2tf_f((xv.w - mu) * r * gv.w + bv.w);
    reinterpret_cast<float4*>(out + (size_t)row * DDIM)[t] = o;
}

// ---------------------------------------------------------------------------
// TF32 GEMM v4: 4-stage cp.async pipeline, conflict-free-by-pitch smem.
// C[M,N] = A[M,K] @ W[K,N] + bias; EPI: 0=bias, 1=bias+residual, 2=bias+GELU
// Block 128x128x16, 256 threads, warp tile 64x32 via m16n8k8 tf32 mma.
// Raw fp32 bits fed to MMA (A pre-rounded by producers; W truncated by hw).
// As[m][k]: pitch AP=20 words -> a-frag banks (mrow*20+kq)%32 all distinct.
// Bs[k][n]: pitch BP=136 words -> b-frag banks (kq*136+mrow)%32 all distinct.
// ---------------------------------------------------------------------------
#define BM 128
#define BN 128
#define BK 16
#define AP 20
#define BP 136
#define NSTAGE 4
#define A_STAGE_W (BM*AP)            // 2560 words
#define B_STAGE_W (BK*BP)            // 2176 words
#define SMEM_WORDS (NSTAGE*(A_STAGE_W + B_STAGE_W))
#define SMEM_BYTES (SMEM_WORDS*4)    // 75776

template <int EPI>
__global__ void __launch_bounds__(256, 2)
gemm_tf32(const float* __restrict__ A, const float* __restrict__ W,
          const float* __restrict__ bias, const float* __restrict__ res,
          float* __restrict__ C, int M, int N, int K) {
    extern __shared__ float smem[];
    float* Abase = smem;                          // [NSTAGE][BM][AP]
    float* Bbase = smem + NSTAGE * A_STAGE_W;     // [NSTAGE][BK][BP]

    int tid = threadIdx.x;
    int bm = blockIdx.y, bn = blockIdx.x;
    int warp = tid >> 5, lane = tid & 31;
    int wm = warp & 1;    // 2 warps along M  -> 64 rows each
    int wn = warp >> 1;   // 4 warps along N  -> 32 cols each
    int mrow = lane >> 2;
    int kq = lane & 3;

    const int m0 = bm * BM, n0 = bn * BN;

    // per-thread cp.async source/dest (2 chunks of A, 2 of B per stage)
    int ar0 = tid >> 2, ac0 = (tid & 3) * 4;
    int ar1 = ar0 + 64;
    int br0 = tid >> 5, bc0 = (tid & 31) * 4;
    int br1 = br0 + 8;
    const float* agp0 = A + (size_t)(m0 + ar0) * K + ac0;
    const float* agp1 = A + (size_t)(m0 + ar1) * K + ac0;
    const float* bgp0 = W + (size_t)br0 * N + n0 + bc0;
    const float* bgp1 = W + (size_t)br1 * N + n0 + bc0;
    uint32_t asm0 = (uint32_t)__cvta_generic_to_shared(Abase + ar0 * AP + ac0);
    uint32_t asm1 = (uint32_t)__cvta_generic_to_shared(Abase + ar1 * AP + ac0);
    uint32_t bsm0 = (uint32_t)__cvta_generic_to_shared(Bbase + br0 * BP + bc0);
    uint32_t bsm1 = (uint32_t)__cvta_generic_to_shared(Bbase + br1 * BP + bc0);
    const uint32_t aStageB = A_STAGE_W * 4;
    const uint32_t bStageB = B_STAGE_W * 4;

    float acc[4][4][4];
#pragma unroll
    for (int i = 0; i < 4; i++)
#pragma unroll
        for (int j = 0; j < 4; j++)
#pragma unroll
            for (int k = 0; k < 4; k++) acc[i][j][k] = 0.f;

    int nk = K / BK;

    auto issue_stage = [&](int it) {
        if (it < nk) {
            int s = it & (NSTAGE - 1);
            int k0 = it * BK;
            cp_async16(asm0 + s * aStageB, agp0 + k0);
            cp_async16(asm1 + s * aStageB, agp1 + k0);
            cp_async16(bsm0 + s * bStageB, bgp0 + (size_t)k0 * N);
            cp_async16(bsm1 + s * bStageB, bgp1 + (size_t)k0 * N);
        }
        cp_commit();   // unconditional: keeps group count exact for wait_group 2
    };

    issue_stage(0);
    issue_stage(1);
    issue_stage(2);

    for (int it = 0; it < nk; it++) {
        cp_wait2();
        __syncthreads();
        issue_stage(it + 3);
        int s = it & (NSTAGE - 1);
        const float* as = Abase + s * A_STAGE_W;
        const float* bs = Bbase + s * B_STAGE_W;
#pragma unroll
        for (int ks = 0; ks < BK; ks += 8) {
            int kr = ks + kq;
            uint32_t a[4][4], b[4][2];
#pragma unroll
            for (int fm = 0; fm < 4; fm++) {
                int mb = wm * 64 + fm * 16 + mrow;
                a[fm][0] = __float_as_uint(as[mb * AP + kr]);
                a[fm][1] = __float_as_uint(as[(mb + 8) * AP + kr]);
                a[fm][2] = __float_as_uint(as[mb * AP + kr + 4]);
                a[fm][3] = __float_as_uint(as[(mb + 8) * AP + kr + 4]);
            }
            int nb = wn * 32 + mrow;
#pragma unroll
            for (int fn = 0; fn < 4; fn++) {
                b[fn][0] = __float_as_uint(bs[kr * BP + nb + fn * 8]);
                b[fn][1] = __float_as_uint(bs[(kr + 4) * BP + nb + fn * 8]);
            }
#pragma unroll
            for (int fm = 0; fm < 4; fm++)
#pragma unroll
                for (int fn = 0; fn < 4; fn++)
                    mma_tf32(acc[fm][fn], a[fm], b[fn], acc[fm][fn]);
        }
        __syncthreads();
    }

    // Epilogue
#pragma unroll
    for (int fm = 0; fm < 4; fm++) {
#pragma unroll
        for (int fn = 0; fn < 4; fn++) {
            int mr = m0 + wm * 64 + fm * 16 + mrow;
            int nc = n0 + wn * 32 + fn * 8 + (kq << 1);
            float bx = bias[nc], by = bias[nc + 1];
            float v0 = acc[fm][fn][0] + bx;
            float v1 = acc[fm][fn][1] + by;
            float v2 = acc[fm][fn][2] + bx;
            float v3 = acc[fm][fn][3] + by;
            if (EPI == 1) {
                v0 += res[(size_t)mr * N + nc];
                v1 += res[(size_t)mr * N + nc + 1];
                v2 += res[(size_t)(mr + 8) * N + nc];
                v3 += res[(size_t)(mr + 8) * N + nc + 1];
            } else if (EPI == 2) {
                v0 = f2tf_f(gelu_exact(v0)); v1 = f2tf_f(gelu_exact(v1));
                v2 = f2tf_f(gelu_exact(v2)); v3 = f2tf_f(gelu_exact(v3));
            }
            *reinterpret_cast<float2*>(C + (size_t)mr * N + nc) = make_float2(v0, v1);
            *reinterpret_cast<float2*>(C + (size_t)(mr + 8) * N + nc) = make_float2(v2, v3);
        }
    }
}

// ---------------------------------------------------------------------------
// Flash attention over parity streams. Output rounded to tf32 grid (feeds
// only the Wout GEMM A-operand).
// ---------------------------------------------------------------------------
#define QP 68
#define KP 40
#define VP 68
#define PP 18

__global__ void __launch_bounds__(128, 4)
attn_flash(const float* __restrict__ qkv, float* __restrict__ out) {
    __shared__ uint32_t Qs[64][QP];
    __shared__ uint32_t Ks[64][KP];
    __shared__ uint32_t Vs[32][VP];
    __shared__ uint32_t Ps[4][32][PP];

    int tid = threadIdx.x;
    int w = tid >> 5, lane = tid & 31;
    int mrow = lane >> 2;
    int kq = lane & 3;

    int qt0 = blockIdx.x * 64;
    int y = blockIdx.y;
    int p = y & 1, h = (y >> 1) & 15, b = y >> 5;

    {
        int r = tid >> 1;
        int d0 = (tid & 1) * 32;
        int l = 2 * (qt0 + r) + p;
        const float* src = qkv + ((size_t)(b * LL + l)) * (3 * DDIM) + h * HDIM + d0;
        int rp = (r & 7) * 8 + (r >> 3);
#pragma unroll
        for (int i = 0; i < 8; i++) {
            float4 v = *reinterpret_cast<const float4*>(src + i * 4);
            int d = d0 + i * 4;
            Qs[d + 0][rp] = f2tf(v.x * 0.125f);
            Qs[d + 1][rp] = f2tf(v.y * 0.125f);
            Qs[d + 2][rp] = f2tf(v.z * 0.125f);
            Qs[d + 3][rp] = f2tf(v.w * 0.125f);
        }
    }

    float m_lo = -1e30f, m_hi = -1e30f, l_lo = 0.f, l_hi = 0.f;
    float o[8][4];
#pragma unroll
    for (int i = 0; i < 8; i++)
#pragma unroll
        for (int j = 0; j < 4; j++) o[i][j] = 0.f;

    int tq_lo = qt0 + 16 * w + mrow;
    int tq_hi = tq_lo + 8;

    int ktbeg = qt0 - 256; if (ktbeg < 0) ktbeg = 0;
    for (int kt0 = ktbeg; kt0 <= qt0 + 32; kt0 += 32) {
        {
            int c = tid >> 2;
            int d0 = (tid & 3) * 16;
            int lk = 2 * (kt0 + c) + p;
            const float* kb = qkv + ((size_t)(b * LL + lk)) * (3 * DDIM) + DDIM + h * HDIM + d0;
            const float* vb = kb + DDIM;
            int cp = (c & 7) * 4 + (c >> 3);
#pragma unroll
            for (int i = 0; i < 4; i++) {
                float4 kv = *reinterpret_cast<const float4*>(kb + i * 4);
                int d = d0 + i * 4;
                Ks[d + 0][cp] = f2tf(kv.x);
                Ks[d + 1][cp] = f2tf(kv.y);
                Ks[d + 2][cp] = f2tf(kv.z);
                Ks[d + 3][cp] = f2tf(kv.w);
                float4 vv = *reinterpret_cast<const float4*>(vb + i * 4);
                Vs[c][((d + 0) & 7) * 8 + ((d + 0) >> 3)] = f2tf(vv.x);
                Vs[c][((d + 1) & 7) * 8 + ((d + 1) >> 3)] = f2tf(vv.y);
                Vs[c][((d + 2) & 7) * 8 + ((d + 2) >> 3)] = f2tf(vv.z);
                Vs[c][((d + 3) & 7) * 8 + ((d + 3) >> 3)] = f2tf(vv.w);
            }
        }
        __syncthreads();

        float s_acc[4][4];
#pragma unroll
        for (int fn = 0; fn < 4; fn++)
#pragma unroll
            for (int j = 0; j < 4; j++) s_acc[fn][j] = 0.f;
#pragma unroll
        for (int ks = 0; ks < 64; ks += 8) {
            int kr = ks + kq;
            uint2 alo = *reinterpret_cast<uint2*>(&Qs[kr][mrow * 8 + 2 * w]);
            uint2 ahi = *reinterpret_cast<uint2*>(&Qs[kr + 4][mrow * 8 + 2 * w]);
            uint32_t a[4] = {alo.x, alo.y, ahi.x, ahi.y};
            uint4 b0 = *reinterpret_cast<uint4*>(&Ks[kr][mrow * 4]);
            uint4 b1 = *reinterpret_cast<uint4*>(&Ks[kr + 4][mrow * 4]);
            uint32_t bb0[4] = {b0.x, b0.y, b0.z, b0.w};
            uint32_t bb1[4] = {b1.x, b1.y, b1.z, b1.w};
#pragma unroll
            for (int fn = 0; fn < 4; fn++) {
                uint32_t bf[2] = {bb0[fn], bb1[fn]};
                mma_tf32(s_acc[fn], a, bf, s_acc[fn]);
            }
        }

        float mt_lo = -1e30f, mt_hi = -1e30f;
#pragma unroll
        for (int fn = 0; fn < 4; fn++) {
#pragma unroll
            for (int j = 0; j < 2; j++) {
                int tk = kt0 + 8 * fn + 2 * kq + j;
                if (!(tk <= tq_lo && tq_lo - tk <= 256)) s_acc[fn][j] = -1e30f;
                if (!(tk <= tq_hi && tq_hi - tk <= 256)) s_acc[fn][2 + j] = -1e30f;
                mt_lo = fmaxf(mt_lo, s_acc[fn][j]);
                mt_hi = fmaxf(mt_hi, s_acc[fn][2 + j]);
            }
        }
        mt_lo = fmaxf(mt_lo, __shfl_xor_sync(~0u, mt_lo, 1));
        mt_lo = fmaxf(mt_lo, __shfl_xor_sync(~0u, mt_lo, 2));
        mt_hi = fmaxf(mt_hi, __shfl_xor_sync(~0u, mt_hi, 1));
        mt_hi = fmaxf(mt_hi, __shfl_xor_sync(~0u, mt_hi, 2));
        float mn_lo = fmaxf(m_lo, mt_lo);
        float mn_hi = fmaxf(m_hi, mt_hi);
        float cf_lo = __expf(m_lo - mn_lo);
        float cf_hi = __expf(m_hi - mn_hi);
        m_lo = mn_lo; m_hi = mn_hi;

        float rs_lo = 0.f, rs_hi = 0.f;
        int rpp = mrow * 2;
#pragma unroll
        for (int fn = 0; fn < 4; fn++) {
#pragma unroll
            for (int j = 0; j < 2; j++) {
                float plo = __expf(s_acc[fn][j] - mn_lo);
                if (s_acc[fn][j] < -1e29f) plo = 0.f;
                float phi = __expf(s_acc[fn][2 + j] - mn_hi);
                if (s_acc[fn][2 + j] < -1e29f) phi = 0.f;
                rs_lo += plo; rs_hi += phi;
                int c = 8 * fn + 2 * kq + j;
                Ps[w][c][rpp] = f2tf(plo);
                Ps[w][c][rpp + 1] = f2tf(phi);
            }
        }
        rs_lo += __shfl_xor_sync(~0u, rs_lo, 1);
        rs_lo += __shfl_xor_sync(~0u, rs_lo, 2);
        rs_hi += __shfl_xor_sync(~0u, rs_hi, 1);
        rs_hi += __shfl_xor_sync(~0u, rs_hi, 2);
        l_lo = l_lo * cf_lo + rs_lo;
        l_hi = l_hi * cf_hi + rs_hi;
#pragma unroll
        for (int fd = 0; fd < 8; fd++) {
            o[fd][0] *= cf_lo; o[fd][1] *= cf_lo;
            o[fd][2] *= cf_hi; o[fd][3] *= cf_hi;
        }
        __syncwarp();

#pragma unroll
        for (int ks = 0; ks < 32; ks += 8) {
            int kr = ks + kq;
            uint2 alo = *reinterpret_cast<uint2*>(&Ps[w][kr][mrow * 2]);
            uint2 ahi = *reinterpret_cast<uint2*>(&Ps[w][kr + 4][mrow * 2]);
            uint32_t a[4] = {alo.x, alo.y, ahi.x, ahi.y};
            uint4 b00 = *reinterpret_cast<uint4*>(&Vs[kr][mrow * 8]);
            uint4 b01 = *reinterpret_cast<uint4*>(&Vs[kr][mrow * 8 + 4]);
            uint4 b10 = *reinterpret_cast<uint4*>(&Vs[kr + 4][mrow * 8]);
            uint4 b11 = *reinterpret_cast<uint4*>(&Vs[kr + 4][mrow * 8 + 4]);
            uint32_t v0[8] = {b00.x, b00.y, b00.z, b00.w, b01.x, b01.y, b01.z, b01.w};
            uint32_t v1[8] = {b10.x, b10.y, b10.z, b10.w, b11.x, b11.y, b11.z, b11.w};
#pragma unroll
            for (int fd = 0; fd < 8; fd++) {
                uint32_t bf[2] = {v0[fd], v1[fd]};
                mma_tf32(o[fd], a, bf, o[fd]);
            }
        }
        __syncthreads();
    }

    float inv_lo = 1.0f / l_lo;
    float inv_hi = 1.0f / l_hi;
    int llo = 2 * tq_lo + p;
    int lhi = 2 * tq_hi + p;
    float* obl = out + ((size_t)(b * LL + llo)) * DDIM + h * HDIM;
    float* obh = out + ((size_t)(b * LL + lhi)) * DDIM + h * HDIM;
#pragma unroll
    for (int fd = 0; fd < 8; fd++) {
        int d = 8 * fd + 2 * kq;
        *reinterpret_cast<float2*>(obl + d) =
            make_float2(f2tf_f(o[fd][0] * inv_lo), f2tf_f(o[fd][1] * inv_lo));
        *reinterpret_cast<float2*>(obh + d) =
            make_float2(f2tf_f(o[fd][2] * inv_hi), f2tf_f(o[fd][3] * inv_hi));
    }
}

// ---------------------------------------------------------------------------
// Launch
// ---------------------------------------------------------------------------
extern "C" void kernel_launch(void* const* d_in, const int* in_sizes, int n_in,
                              void* d_out, int out_size) {
    const float* x     = (const float*)d_in[0];
    const float* ln1_g = (const float*)d_in[1];
    const float* ln1_b = (const float*)d_in[2];
    const float* Wqkv  = (const float*)d_in[3];
    const float* bqkv  = (const float*)d_in[4];
    const float* Wout  = (const float*)d_in[5];
    const float* bout  = (const float*)d_in[6];
    const float* ln2_g = (const float*)d_in[7];
    const float* ln2_b = (const float*)d_in[8];
    const float* W1    = (const float*)d_in[9];
    const float* b1    = (const float*)d_in[10];
    const float* W2    = (const float*)d_in[11];
    const float* b2    = (const float*)d_in[12];
    float* out = (float*)d_out;

    float *h, *qkv, *attn, *x1, *f;
    cudaGetSymbolAddress((void**)&h, g_h);
    cudaGetSymbolAddress((void**)&qkv, g_qkv);
    cudaGetSymbolAddress((void**)&attn, g_attn);
    cudaGetSymbolAddress((void**)&x1, g_x1);
    cudaGetSymbolAddress((void**)&f, g_f);

    static int smem_set = 0;
    if (!smem_set) {
        cudaFuncSetAttribute(gemm_tf32<0>, cudaFuncAttributeMaxDynamicSharedMemorySize, SMEM_BYTES);
        cudaFuncSetAttribute(gemm_tf32<1>, cudaFuncAttributeMaxDynamicSharedMemorySize, SMEM_BYTES);
        cudaFuncSetAttribute(gemm_tf32<2>, cudaFuncAttributeMaxDynamicSharedMemorySize, SMEM_BYTES);
        smem_set = 1;
    }

    // 1. LN1
    ln_kernel<<<MM, 256>>>(x, ln1_g, ln1_b, h);
    // 2. QKV = h @ Wqkv + bqkv          [4096,1024]x[1024,3072]
    gemm_tf32<0><<<dim3(3 * DDIM / BN, MM / BM), 256, SMEM_BYTES>>>(
        h, Wqkv, bqkv, nullptr, qkv, MM, 3 * DDIM, DDIM);
    // 3. attention (flash, parity streams)
    attn_flash<<<dim3(16, 64), 128>>>(qkv, attn);
    // 4. x1 = x + attn @ Wout + bout    [4096,1024]x[1024,1024]
    gemm_tf32<1><<<dim3(DDIM / BN, MM / BM), 256, SMEM_BYTES>>>(
        attn, Wout, bout, x, x1, MM, DDIM, DDIM);
    // 5. LN2
    ln_kernel<<<MM, 256>>>(x1, ln2_g, ln2_b, h);
    // 6. f = gelu(h @ W1 + b1)          [4096,1024]x[1024,4096]
    gemm_tf32<2><<<dim3(4 * DDIM / BN, MM / BM), 256, SMEM_BYTES>>>(
        h, W1, b1, nullptr, f, MM, 4 * DDIM, DDIM);
    // 7. out = x1 + f @ W2 + b2         [4096,4096]x[4096,1024]
    gemm_tf32<1><<<dim3(DDIM / BN, MM / BM), 256, SMEM_BYTES>>>(
        f, W2, b2, x1, out, MM, DDIM, 4 * DDIM);
}

// round 6
// speedup vs baseline: 3.1942x; 1.5018x over previous
#include <cuda_runtime.h>
#include <cuda_fp16.h>
#include <cstdint>
#include <math.h>

// Problem constants
#define BB 2
#define LL 2048
#define DDIM 1024
#define HH 16
#define HDIM 64
#define MM (BB*LL)          // 4096 rows
#define WIN 512
#define DIL 2

// Scratch (device globals; no allocation allowed)
__device__ __half g_h[(size_t)MM*DDIM];          // LN output (fp16)
__device__ __half g_qkv[(size_t)MM*3*DDIM];      // QKV (fp16)
__device__ __half g_attn[(size_t)MM*DDIM];       // attention output (fp16)
__device__ float  g_x1[(size_t)MM*DDIM];         // x + attn@Wout (fp32, residual)
__device__ __half g_f[(size_t)MM*4*DDIM];        // FFN hidden (fp16)
__device__ __half g_wt[(size_t)12582912];        // transposed weights, N-major fp16
#define WT_QKV 0
#define WT_OUT 3145728
#define WT_W1  4194304
#define WT_W2  8388608

__device__ __forceinline__ uint32_t f2tf(float x) {
    uint32_t r;
    asm("cvt.rna.tf32.f32 %0, %1;" : "=r"(r) : "f"(x));
    return r;
}

__device__ __forceinline__ void mma_tf32(float d[4], const uint32_t a[4],
                                         const uint32_t b[2], const float c[4]) {
    asm volatile(
        "mma.sync.aligned.m16n8k8.row.col.f32.tf32.tf32.f32 "
        "{%0,%1,%2,%3}, {%4,%5,%6,%7}, {%8,%9}, {%10,%11,%12,%13};\n"
        : "=f"(d[0]), "=f"(d[1]), "=f"(d[2]), "=f"(d[3])
        : "r"(a[0]), "r"(a[1]), "r"(a[2]), "r"(a[3]),
          "r"(b[0]), "r"(b[1]),
          "f"(c[0]), "f"(c[1]), "f"(c[2]), "f"(c[3]));
}

__device__ __forceinline__ void mma_fp16(float d[4], const uint32_t a[4],
                                         uint32_t b0, uint32_t b1) {
    asm volatile(
        "mma.sync.aligned.m16n8k16.row.col.f32.f16.f16.f32 "
        "{%0,%1,%2,%3}, {%4,%5,%6,%7}, {%8,%9}, {%0,%1,%2,%3};\n"
        : "+f"(d[0]), "+f"(d[1]), "+f"(d[2]), "+f"(d[3])
        : "r"(a[0]), "r"(a[1]), "r"(a[2]), "r"(a[3]),
          "r"(b0), "r"(b1));
}

__device__ __forceinline__ void ldsm_x4(uint32_t r[4], uint32_t addr) {
    asm volatile("ldmatrix.sync.aligned.m8n8.x4.shared.b16 {%0,%1,%2,%3}, [%4];"
                 : "=r"(r[0]), "=r"(r[1]), "=r"(r[2]), "=r"(r[3]) : "r"(addr));
}

__device__ __forceinline__ float gelu_exact(float x) {
    return 0.5f * x * (1.0f + erff(x * 0.70710678118654752f));
}

__device__ __forceinline__ void cp_async16(uint32_t smem_addr, const void* gptr) {
    asm volatile("cp.async.cg.shared.global [%0], [%1], 16;\n"
                 :: "r"(smem_addr), "l"(gptr));
}
__device__ __forceinline__ void cp_commit() {
    asm volatile("cp.async.commit_group;\n");
}
__device__ __forceinline__ void cp_wait2() {
    asm volatile("cp.async.wait_group 2;\n");
}
__device__ __forceinline__ uint32_t smem_u32(const void* p) {
    uint32_t a;
    asm("{ .reg .u64 t; cvta.to.shared.u64 t, %1; cvt.u32.u64 %0, t; }"
        : "=r"(a) : "l"(p));
    return a;
}

__device__ __forceinline__ void store2(__half* p, float a, float b) {
    *reinterpret_cast<__half2*>(p) = __floats2half2_rn(a, b);
}
__device__ __forceinline__ void store2(float* p, float a, float b) {
    *reinterpret_cast<float2*>(p) = make_float2(a, b);
}

// ---------------------------------------------------------------------------
// Weight transpose: out[n][k] = fp16(in[k][n]).  in: [R][C] fp32, out: [C][R]
// ---------------------------------------------------------------------------
__global__ void transpose_h(const float* __restrict__ in, __half* __restrict__ out,
                            int R, int C) {
    __shared__ float tile[32][33];
    int c0 = blockIdx.x * 32, r0 = blockIdx.y * 32;
    int tx = threadIdx.x, ty = threadIdx.y;   // 32 x 8
#pragma unroll
    for (int i = 0; i < 32; i += 8)
        tile[ty + i][tx] = in[(size_t)(r0 + ty + i) * C + c0 + tx];
    __syncthreads();
#pragma unroll
    for (int i = 0; i < 32; i += 8)
        out[(size_t)(c0 + ty + i) * R + r0 + tx] = __float2half_rn(tile[tx][ty + i]);
}

// ---------------------------------------------------------------------------
// LayerNorm: one block (256 threads) per row of 1024 floats -> fp16 out
// ---------------------------------------------------------------------------
__global__ void ln_kernel(const float* __restrict__ x, const float* __restrict__ g,
                          const float* __restrict__ b, __half* __restrict__ out) {
    int row = blockIdx.x;
    int t = threadIdx.x;
    const float4 xv = reinterpret_cast<const float4*>(x + (size_t)row * DDIM)[t];

    __shared__ float warp_s[8], warp_q[8];
    __shared__ float s_mu, s_r;

    float s = xv.x + xv.y + xv.z + xv.w;
    float q = xv.x*xv.x + xv.y*xv.y + xv.z*xv.z + xv.w*xv.w;
#pragma unroll
    for (int o = 16; o; o >>= 1) {
        s += __shfl_xor_sync(~0u, s, o);
        q += __shfl_xor_sync(~0u, q, o);
    }
    if ((t & 31) == 0) { warp_s[t >> 5] = s; warp_q[t >> 5] = q; }
    __syncthreads();
    if (t == 0) {
        float S = 0.f, Q = 0.f;
#pragma unroll
        for (int i = 0; i < 8; i++) { S += warp_s[i]; Q += warp_q[i]; }
        float mu = S * (1.0f / DDIM);
        float var = Q * (1.0f / DDIM) - mu * mu;
        s_mu = mu;
        s_r = rsqrtf(var + 1e-5f);
    }
    __syncthreads();
    float mu = s_mu, r = s_r;
    float4 gv = reinterpret_cast<const float4*>(g)[t];
    float4 bv = reinterpret_cast<const float4*>(b)[t];
    __half2 o01 = __floats2half2_rn((xv.x - mu) * r * gv.x + bv.x,
                                    (xv.y - mu) * r * gv.y + bv.y);
    __half2 o23 = __floats2half2_rn((xv.z - mu) * r * gv.z + bv.z,
                                    (xv.w - mu) * r * gv.w + bv.w);
    uint2 pk;
    pk.x = *reinterpret_cast<uint32_t*>(&o01);
    pk.y = *reinterpret_cast<uint32_t*>(&o23);
    *reinterpret_cast<uint2*>(out + (size_t)row * DDIM + t * 4) = pk;
}

// ---------------------------------------------------------------------------
// FP16 GEMM: C[M,N] = A[M,K] @ Wt[N,K]^T + bias
// EPI: 0=bias, 1=bias+residual, 2=bias+GELU.  OUT: __half or float.
// Block 128x128x32, 256 threads, warp tile 64x32 via m16n8k16 fp16 mma.
// Smem rows pitch 40 halves (80B): conflict-free cp.async STS and ldmatrix.
// 4-stage cp.async pipeline, wait_group 2, one __syncthreads per K-iter.
// ---------------------------------------------------------------------------
#define FSTG 10240                    // bytes per operand stage: 128 rows * 80B
#define FNST 4
#define FSMEM (FNST*2*FSTG)           // 81920 bytes

template <int EPI, typename OUT>
__global__ void __launch_bounds__(256)
gemm_fp16(const __half* __restrict__ A, const __half* __restrict__ Wt,
          const float* __restrict__ bias, const float* __restrict__ res,
          OUT* __restrict__ C, int M, int N, int K) {
    extern __shared__ char dsm[];
    uint32_t base = smem_u32(dsm);

    int tid = threadIdx.x;
    int warp = tid >> 5, lane = tid & 31;
    int wm = warp & 1;    // 2 warps along M -> 64 rows
    int wn = warp >> 1;   // 4 warps along N -> 32 cols
    int mrow = lane >> 2, kq = lane & 3;
    int m0 = blockIdx.y * 128, n0 = blockIdx.x * 128;

    // cp.async: 512 16B-chunks per operand per stage; 2 per thread per operand
    int ch0 = tid, ch1 = tid + 256;
    int ar0 = ch0 >> 2, ac0 = (ch0 & 3) * 8;
    int ar1 = ch1 >> 2, ac1 = (ch1 & 3) * 8;
    const __half* agp0 = A + (size_t)(m0 + ar0) * K + ac0;
    const __half* agp1 = A + (size_t)(m0 + ar1) * K + ac1;
    const __half* bgp0 = Wt + (size_t)(n0 + ar0) * K + ac0;
    const __half* bgp1 = Wt + (size_t)(n0 + ar1) * K + ac1;
    uint32_t ad0 = base + ar0 * 80 + ac0 * 2;
    uint32_t ad1 = base + ar1 * 80 + ac1 * 2;
    uint32_t bd0 = ad0 + FNST * FSTG;
    uint32_t bd1 = ad1 + FNST * FSTG;

    float acc[4][4][4];
#pragma unroll
    for (int i = 0; i < 4; i++)
#pragma unroll
        for (int j = 0; j < 4; j++)
#pragma unroll
            for (int k = 0; k < 4; k++) acc[i][j][k] = 0.f;

    int nk = K / 32;
    auto issue = [&](int it) {
        if (it < nk) {
            int s = it & 3;
            int k0 = it * 32;
            cp_async16(ad0 + s * FSTG, agp0 + k0);
            cp_async16(ad1 + s * FSTG, agp1 + k0);
            cp_async16(bd0 + s * FSTG, bgp0 + k0);
            cp_async16(bd1 + s * FSTG, bgp1 + k0);
        }
        cp_commit();
    };
    issue(0); issue(1); issue(2);

    int lrow = lane & 15;          // ldmatrix: row within 16
    int lcolB = (lane >> 4) * 16;  // 0 or 8 halves -> bytes

    for (int it = 0; it < nk; it++) {
        cp_wait2();
        __syncthreads();
        issue(it + 3);
        int s = it & 3;
        uint32_t aST = base + s * FSTG;
        uint32_t bST = aST + FNST * FSTG;
#pragma unroll
        for (int ks = 0; ks < 32; ks += 16) {
            uint32_t a[4][4], b[2][4];
#pragma unroll
            for (int fm = 0; fm < 4; fm++)
                ldsm_x4(a[fm], aST + (wm * 64 + fm * 16 + lrow) * 80 + ks * 2 + lcolB);
#pragma unroll
            for (int p = 0; p < 2; p++)
                ldsm_x4(b[p], bST + (wn * 32 + p * 16 + lrow) * 80 + ks * 2 + lcolB);
#pragma unroll
            for (int fm = 0; fm < 4; fm++)
#pragma unroll
                for (int fn = 0; fn < 4; fn++)
                    mma_fp16(acc[fm][fn], a[fm],
                             b[fn >> 1][fn & 1], b[fn >> 1][2 + (fn & 1)]);
        }
    }

    // Epilogue
#pragma unroll
    for (int fm = 0; fm < 4; fm++) {
#pragma unroll
        for (int fn = 0; fn < 4; fn++) {
            int mr = m0 + wm * 64 + fm * 16 + mrow;
            int nc = n0 + wn * 32 + fn * 8 + (kq << 1);
            float bx = bias[nc], by = bias[nc + 1];
            float v0 = acc[fm][fn][0] + bx;
            float v1 = acc[fm][fn][1] + by;
            float v2 = acc[fm][fn][2] + bx;
            float v3 = acc[fm][fn][3] + by;
            if (EPI == 1) {
                v0 += res[(size_t)mr * N + nc];
                v1 += res[(size_t)mr * N + nc + 1];
                v2 += res[(size_t)(mr + 8) * N + nc];
                v3 += res[(size_t)(mr + 8) * N + nc + 1];
            } else if (EPI == 2) {
                v0 = gelu_exact(v0); v1 = gelu_exact(v1);
                v2 = gelu_exact(v2); v3 = gelu_exact(v3);
            }
            store2(C + (size_t)mr * N + nc, v0, v1);
            store2(C + (size_t)(mr + 8) * N + nc, v2, v3);
        }
    }
}

// ---------------------------------------------------------------------------
// Flash attention over parity streams (tf32 mma internals, fp16 I/O).
// ---------------------------------------------------------------------------
#define QP 68
#define KP 40
#define VP 68
#define PP 18

__global__ void __launch_bounds__(128, 4)
attn_flash(const __half* __restrict__ qkv, __half* __restrict__ out) {
    __shared__ uint32_t Qs[64][QP];
    __shared__ uint32_t Ks[64][KP];
    __shared__ uint32_t Vs[32][VP];
    __shared__ uint32_t Ps[4][32][PP];

    int tid = threadIdx.x;
    int w = tid >> 5, lane = tid & 31;
    int mrow = lane >> 2;
    int kq = lane & 3;

    int qt0 = blockIdx.x * 64;
    int y = blockIdx.y;
    int p = y & 1, h = (y >> 1) & 15, b = y >> 5;

    {
        int r = tid >> 1;
        int d0 = (tid & 1) * 32;
        int l = 2 * (qt0 + r) + p;
        const __half* src = qkv + ((size_t)(b * LL + l)) * (3 * DDIM) + h * HDIM + d0;
        int rp = (r & 7) * 8 + (r >> 3);
#pragma unroll
        for (int i = 0; i < 4; i++) {
            uint4 v8 = reinterpret_cast<const uint4*>(src)[i];
            const __half2* hp = reinterpret_cast<const __half2*>(&v8);
#pragma unroll
            for (int j = 0; j < 4; j++) {
                float2 f = __half22float2(hp[j]);
                int d = d0 + i * 8 + j * 2;
                Qs[d][rp] = f2tf(f.x * 0.125f);
                Qs[d + 1][rp] = f2tf(f.y * 0.125f);
            }
        }
    }

    float m_lo = -1e30f, m_hi = -1e30f, l_lo = 0.f, l_hi = 0.f;
    float o[8][4];
#pragma unroll
    for (int i = 0; i < 8; i++)
#pragma unroll
        for (int j = 0; j < 4; j++) o[i][j] = 0.f;

    int tq_lo = qt0 + 16 * w + mrow;
    int tq_hi = tq_lo + 8;

    int ktbeg = qt0 - 256; if (ktbeg < 0) ktbeg = 0;
    for (int kt0 = ktbeg; kt0 <= qt0 + 32; kt0 += 32) {
        {
            int c = tid >> 2;
            int d0 = (tid & 3) * 16;
            int lk = 2 * (kt0 + c) + p;
            const __half* kb = qkv + ((size_t)(b * LL + lk)) * (3 * DDIM) + DDIM + h * HDIM + d0;
            const __half* vb = kb + DDIM;
            int cp = (c & 7) * 4 + (c >> 3);
#pragma unroll
            for (int i = 0; i < 2; i++) {
                uint4 k8 = reinterpret_cast<const uint4*>(kb)[i];
                uint4 v8 = reinterpret_cast<const uint4*>(vb)[i];
                const __half2* khp = reinterpret_cast<const __half2*>(&k8);
                const __half2* vhp = reinterpret_cast<const __half2*>(&v8);
#pragma unroll
                for (int j = 0; j < 4; j++) {
                    float2 kf = __half22float2(khp[j]);
                    float2 vf = __half22float2(vhp[j]);
                    int d = d0 + i * 8 + j * 2;
                    Ks[d][cp] = f2tf(kf.x);
                    Ks[d + 1][cp] = f2tf(kf.y);
                    Vs[c][(d & 7) * 8 + (d >> 3)] = f2tf(vf.x);
                    Vs[c][((d + 1) & 7) * 8 + ((d + 1) >> 3)] = f2tf(vf.y);
                }
            }
        }
        __syncthreads();

        float s_acc[4][4];
#pragma unroll
        for (int fn = 0; fn < 4; fn++)
#pragma unroll
            for (int j = 0; j < 4; j++) s_acc[fn][j] = 0.f;
#pragma unroll
        for (int ks = 0; ks < 64; ks += 8) {
            int kr = ks + kq;
            uint2 alo = *reinterpret_cast<uint2*>(&Qs[kr][mrow * 8 + 2 * w]);
            uint2 ahi = *reinterpret_cast<uint2*>(&Qs[kr + 4][mrow * 8 + 2 * w]);
            uint32_t a[4] = {alo.x, alo.y, ahi.x, ahi.y};
            uint4 b0 = *reinterpret_cast<uint4*>(&Ks[kr][mrow * 4]);
            uint4 b1 = *reinterpret_cast<uint4*>(&Ks[kr + 4][mrow * 4]);
            uint32_t bb0[4] = {b0.x, b0.y, b0.z, b0.w};
            uint32_t bb1[4] = {b1.x, b1.y, b1.z, b1.w};
#pragma unroll
            for (int fn = 0; fn < 4; fn++) {
                uint32_t bf[2] = {bb0[fn], bb1[fn]};
                mma_tf32(s_acc[fn], a, bf, s_acc[fn]);
            }
        }

        float mt_lo = -1e30f, mt_hi = -1e30f;
#pragma unroll
        for (int fn = 0; fn < 4; fn++) {
#pragma unroll
            for (int j = 0; j < 2; j++) {
                int tk = kt0 + 8 * fn + 2 * kq + j;
                if (!(tk <= tq_lo && tq_lo - tk <= 256)) s_acc[fn][j] = -1e30f;
                if (!(tk <= tq_hi && tq_hi - tk <= 256)) s_acc[fn][2 + j] = -1e30f;
                mt_lo = fmaxf(mt_lo, s_acc[fn][j]);
                mt_hi = fmaxf(mt_hi, s_acc[fn][2 + j]);
            }
        }
        mt_lo = fmaxf(mt_lo, __shfl_xor_sync(~0u, mt_lo, 1));
        mt_lo = fmaxf(mt_lo, __shfl_xor_sync(~0u, mt_lo, 2));
        mt_hi = fmaxf(mt_hi, __shfl_xor_sync(~0u, mt_hi, 1));
        mt_hi = fmaxf(mt_hi, __shfl_xor_sync(~0u, mt_hi, 2));
        float mn_lo = fmaxf(m_lo, mt_lo);
        float mn_hi = fmaxf(m_hi, mt_hi);
        float cf_lo = __expf(m_lo - mn_lo);
        float cf_hi = __expf(m_hi - mn_hi);
        m_lo = mn_lo; m_hi = mn_hi;

        float rs_lo = 0.f, rs_hi = 0.f;
        int rpp = mrow * 2;
#pragma unroll
        for (int fn = 0; fn < 4; fn++) {
#pragma unroll
            for (int j = 0; j < 2; j++) {
                float plo = __expf(s_acc[fn][j] - mn_lo);
                if (s_acc[fn][j] < -1e29f) plo = 0.f;
                float phi = __expf(s_acc[fn][2 + j] - mn_hi);
                if (s_acc[fn][2 + j] < -1e29f) phi = 0.f;
                rs_lo += plo; rs_hi += phi;
                int c = 8 * fn + 2 * kq + j;
                Ps[w][c][rpp] = f2tf(plo);
                Ps[w][c][rpp + 1] = f2tf(phi);
            }
        }
        rs_lo += __shfl_xor_sync(~0u, rs_lo, 1);
        rs_lo += __shfl_xor_sync(~0u, rs_lo, 2);
        rs_hi += __shfl_xor_sync(~0u, rs_hi, 1);
        rs_hi += __shfl_xor_sync(~0u, rs_hi, 2);
        l_lo = l_lo * cf_lo + rs_lo;
        l_hi = l_hi * cf_hi + rs_hi;
#pragma unroll
        for (int fd = 0; fd < 8; fd++) {
            o[fd][0] *= cf_lo; o[fd][1] *= cf_lo;
            o[fd][2] *= cf_hi; o[fd][3] *= cf_hi;
        }
        __syncwarp();

#pragma unroll
        for (int ks = 0; ks < 32; ks += 8) {
            int kr = ks + kq;
            uint2 alo = *reinterpret_cast<uint2*>(&Ps[w][kr][mrow * 2]);
            uint2 ahi = *reinterpret_cast<uint2*>(&Ps[w][kr + 4][mrow * 2]);
            uint32_t a[4] = {alo.x, alo.y, ahi.x, ahi.y};
            uint4 b00 = *reinterpret_cast<uint4*>(&Vs[kr][mrow * 8]);
            uint4 b01 = *reinterpret_cast<uint4*>(&Vs[kr][mrow * 8 + 4]);
            uint4 b10 = *reinterpret_cast<uint4*>(&Vs[kr + 4][mrow * 8]);
            uint4 b11 = *reinterpret_cast<uint4*>(&Vs[kr + 4][mrow * 8 + 4]);
            uint32_t v0[8] = {b00.x, b00.y, b00.z, b00.w, b01.x, b01.y, b01.z, b01.w};
            uint32_t v1[8] = {b10.x, b10.y, b10.z, b10.w, b11.x, b11.y, b11.z, b11.w};
#pragma unroll
            for (int fd = 0; fd < 8; fd++) {
                uint32_t bf[2] = {v0[fd], v1[fd]};
                mma_tf32(o[fd], a, bf, o[fd]);
            }
        }
        __syncthreads();
    }

    float inv_lo = 1.0f / l_lo;
    float inv_hi = 1.0f / l_hi;
    int llo = 2 * tq_lo + p;
    int lhi = 2 * tq_hi + p;
    __half* obl = out + ((size_t)(b * LL + llo)) * DDIM + h * HDIM;
    __half* obh = out + ((size_t)(b * LL + lhi)) * DDIM + h * HDIM;
#pragma unroll
    for (int fd = 0; fd < 8; fd++) {
        int d = 8 * fd + 2 * kq;
        store2(obl + d, o[fd][0] * inv_lo, o[fd][1] * inv_lo);
        store2(obh + d, o[fd][2] * inv_hi, o[fd][3] * inv_hi);
    }
}

// ---------------------------------------------------------------------------
// Launch
// ---------------------------------------------------------------------------
extern "C" void kernel_launch(void* const* d_in, const int* in_sizes, int n_in,
                              void* d_out, int out_size) {
    const float* x     = (const float*)d_in[0];
    const float* ln1_g = (const float*)d_in[1];
    const float* ln1_b = (const float*)d_in[2];
    const float* Wqkv  = (const float*)d_in[3];
    const float* bqkv  = (const float*)d_in[4];
    const float* Wout  = (const float*)d_in[5];
    const float* bout  = (const float*)d_in[6];
    const float* ln2_g = (const float*)d_in[7];
    const float* ln2_b = (const float*)d_in[8];
    const float* W1    = (const float*)d_in[9];
    const float* b1    = (const float*)d_in[10];
    const float* W2    = (const float*)d_in[11];
    const float* b2    = (const float*)d_in[12];
    float* out = (float*)d_out;

    __half *h, *qkv, *attn, *f, *wt;
    float *x1;
    cudaGetSymbolAddress((void**)&h, g_h);
    cudaGetSymbolAddress((void**)&qkv, g_qkv);
    cudaGetSymbolAddress((void**)&attn, g_attn);
    cudaGetSymbolAddress((void**)&x1, g_x1);
    cudaGetSymbolAddress((void**)&f, g_f);
    cudaGetSymbolAddress((void**)&wt, g_wt);

    static int smem_set = 0;
    if (!smem_set) {
        cudaFuncSetAttribute(gemm_fp16<0, __half>,
                             cudaFuncAttributeMaxDynamicSharedMemorySize, FSMEM);
        cudaFuncSetAttribute(gemm_fp16<1, float>,
                             cudaFuncAttributeMaxDynamicSharedMemorySize, FSMEM);
        cudaFuncSetAttribute(gemm_fp16<2, __half>,
                             cudaFuncAttributeMaxDynamicSharedMemorySize, FSMEM);
        smem_set = 1;
    }

    dim3 tb(32, 8);
    // 0. transpose weights (N-major, fp16)
    transpose_h<<<dim3(3 * DDIM / 32, DDIM / 32), tb>>>(Wqkv, wt + WT_QKV, DDIM, 3 * DDIM);
    transpose_h<<<dim3(DDIM / 32, DDIM / 32), tb>>>(Wout, wt + WT_OUT, DDIM, DDIM);
    transpose_h<<<dim3(4 * DDIM / 32, DDIM / 32), tb>>>(W1, wt + WT_W1, DDIM, 4 * DDIM);
    transpose_h<<<dim3(DDIM / 32, 4 * DDIM / 32), tb>>>(W2, wt + WT_W2, 4 * DDIM, DDIM);

    // 1. LN1
    ln_kernel<<<MM, 256>>>(x, ln1_g, ln1_b, h);
    // 2. QKV = h @ Wqkv + bqkv
    gemm_fp16<0, __half><<<dim3(24, 32), 256, FSMEM>>>(
        h, wt + WT_QKV, bqkv, nullptr, qkv, MM, 3 * DDIM, DDIM);
    // 3. attention
    attn_flash<<<dim3(16, 64), 128>>>(qkv, attn);
    // 4. x1 = x + attn @ Wout + bout
    gemm_fp16<1, float><<<dim3(8, 32), 256, FSMEM>>>(
        attn, wt + WT_OUT, bout, x, x1, MM, DDIM, DDIM);
    // 5. LN2
    ln_kernel<<<MM, 256>>>(x1, ln2_g, ln2_b, h);
    // 6. f = gelu(h @ W1 + b1)
    gemm_fp16<2, __half><<<dim3(32, 32), 256, FSMEM>>>(
        h, wt + WT_W1, b1, nullptr, f, MM, 4 * DDIM, DDIM);
    // 7. out = x1 + f @ W2 + b2
    gemm_fp16<1, float><<<dim3(8, 32), 256, FSMEM>>>(
        f, wt + WT_W2, b2, x1, out, MM, DDIM, 4 * DDIM);
}

// round 7
// speedup vs baseline: 3.8071x; 1.1919x over previous
#include <cuda_runtime.h>
#include <cuda_fp16.h>
#include <cstdint>
#include <math.h>

// Problem constants
#define BB 2
#define LL 2048
#define DDIM 1024
#define HH 16
#define HDIM 64
#define MM (BB*LL)          // 4096 rows
#define WIN 512
#define DIL 2

// Scratch (device globals; no allocation allowed)
__device__ __half g_h[(size_t)MM*DDIM];          // LN output (fp16)
__device__ __half g_qkv[(size_t)MM*3*DDIM];      // QKV (fp16)
__device__ __half g_attn[(size_t)MM*DDIM];       // attention output (fp16)
__device__ float  g_x1[(size_t)MM*DDIM];         // x + attn@Wout (fp32, residual)
__device__ __half g_f[(size_t)MM*4*DDIM];        // FFN hidden (fp16)
__device__ __half g_wt[(size_t)12582912];        // transposed weights, N-major fp16
#define WT_QKV 0
#define WT_OUT 3145728
#define WT_W1  4194304
#define WT_W2  8388608

__device__ __forceinline__ void mma_fp16(float d[4], const uint32_t a[4],
                                         uint32_t b0, uint32_t b1) {
    asm volatile(
        "mma.sync.aligned.m16n8k16.row.col.f32.f16.f16.f32 "
        "{%0,%1,%2,%3}, {%4,%5,%6,%7}, {%8,%9}, {%0,%1,%2,%3};\n"
        : "+f"(d[0]), "+f"(d[1]), "+f"(d[2]), "+f"(d[3])
        : "r"(a[0]), "r"(a[1]), "r"(a[2]), "r"(a[3]),
          "r"(b0), "r"(b1));
}

__device__ __forceinline__ void ldsm_x4(uint32_t r[4], uint32_t addr) {
    asm volatile("ldmatrix.sync.aligned.m8n8.x4.shared.b16 {%0,%1,%2,%3}, [%4];"
                 : "=r"(r[0]), "=r"(r[1]), "=r"(r[2]), "=r"(r[3]) : "r"(addr));
}
__device__ __forceinline__ void ldsm_x4_t(uint32_t r[4], uint32_t addr) {
    asm volatile("ldmatrix.sync.aligned.m8n8.x4.trans.shared.b16 {%0,%1,%2,%3}, [%4];"
                 : "=r"(r[0]), "=r"(r[1]), "=r"(r[2]), "=r"(r[3]) : "r"(addr));
}

__device__ __forceinline__ float gelu_exact(float x) {
    return 0.5f * x * (1.0f + erff(x * 0.70710678118654752f));
}

__device__ __forceinline__ void cp_async16(uint32_t smem_addr, const void* gptr) {
    asm volatile("cp.async.cg.shared.global [%0], [%1], 16;\n"
                 :: "r"(smem_addr), "l"(gptr));
}
__device__ __forceinline__ void cp_commit() {
    asm volatile("cp.async.commit_group;\n");
}
__device__ __forceinline__ void cp_wait2() {
    asm volatile("cp.async.wait_group 2;\n");
}
__device__ __forceinline__ uint32_t smem_u32(const void* p) {
    uint32_t a;
    asm("{ .reg .u64 t; cvta.to.shared.u64 t, %1; cvt.u32.u64 %0, t; }"
        : "=r"(a) : "l"(p));
    return a;
}

__device__ __forceinline__ void store2(__half* p, float a, float b) {
    *reinterpret_cast<__half2*>(p) = __floats2half2_rn(a, b);
}
__device__ __forceinline__ void store2(float* p, float a, float b) {
    *reinterpret_cast<float2*>(p) = make_float2(a, b);
}

// ---------------------------------------------------------------------------
// Weight transpose: out[n][k] = fp16(in[k][n]).  in: [R][C] fp32, out: [C][R]
// ---------------------------------------------------------------------------
__global__ void transpose_h(const float* __restrict__ in, __half* __restrict__ out,
                            int R, int C) {
    __shared__ float tile[32][33];
    int c0 = blockIdx.x * 32, r0 = blockIdx.y * 32;
    int tx = threadIdx.x, ty = threadIdx.y;   // 32 x 8
#pragma unroll
    for (int i = 0; i < 32; i += 8)
        tile[ty + i][tx] = in[(size_t)(r0 + ty + i) * C + c0 + tx];
    __syncthreads();
#pragma unroll
    for (int i = 0; i < 32; i += 8)
        out[(size_t)(c0 + ty + i) * R + r0 + tx] = __float2half_rn(tile[tx][ty + i]);
}

// ---------------------------------------------------------------------------
// LayerNorm: one block (256 threads) per row of 1024 floats -> fp16 out
// ---------------------------------------------------------------------------
__global__ void ln_kernel(const float* __restrict__ x, const float* __restrict__ g,
                          const float* __restrict__ b, __half* __restrict__ out) {
    int row = blockIdx.x;
    int t = threadIdx.x;
    const float4 xv = reinterpret_cast<const float4*>(x + (size_t)row * DDIM)[t];

    __shared__ float warp_s[8], warp_q[8];
    __shared__ float s_mu, s_r;

    float s = xv.x + xv.y + xv.z + xv.w;
    float q = xv.x*xv.x + xv.y*xv.y + xv.z*xv.z + xv.w*xv.w;
#pragma unroll
    for (int o = 16; o; o >>= 1) {
        s += __shfl_xor_sync(~0u, s, o);
        q += __shfl_xor_sync(~0u, q, o);
    }
    if ((t & 31) == 0) { warp_s[t >> 5] = s; warp_q[t >> 5] = q; }
    __syncthreads();
    if (t == 0) {
        float S = 0.f, Q = 0.f;
#pragma unroll
        for (int i = 0; i < 8; i++) { S += warp_s[i]; Q += warp_q[i]; }
        float mu = S * (1.0f / DDIM);
        float var = Q * (1.0f / DDIM) - mu * mu;
        s_mu = mu;
        s_r = rsqrtf(var + 1e-5f);
    }
    __syncthreads();
    float mu = s_mu, r = s_r;
    float4 gv = reinterpret_cast<const float4*>(g)[t];
    float4 bv = reinterpret_cast<const float4*>(b)[t];
    __half2 o01 = __floats2half2_rn((xv.x - mu) * r * gv.x + bv.x,
                                    (xv.y - mu) * r * gv.y + bv.y);
    __half2 o23 = __floats2half2_rn((xv.z - mu) * r * gv.z + bv.z,
                                    (xv.w - mu) * r * gv.w + bv.w);
    uint2 pk;
    pk.x = *reinterpret_cast<uint32_t*>(&o01);
    pk.y = *reinterpret_cast<uint32_t*>(&o23);
    *reinterpret_cast<uint2*>(out + (size_t)row * DDIM + t * 4) = pk;
}

// ---------------------------------------------------------------------------
// FP16 GEMM: C[M,N] = A[M,K] @ Wt[N,K]^T + bias
// EPI: 0=bias, 1=bias+residual, 2=bias+GELU.  OUT: __half or float.
// Block 128x128x32, 256 threads (2 CTA/SM), warp tile 64x32, m16n8k16.
// ---------------------------------------------------------------------------
#define FSTG 10240                    // bytes per operand stage: 128 rows * 80B
#define FNST 4
#define FSMEM (FNST*2*FSTG)           // 81920 bytes

template <int EPI, typename OUT>
__global__ void __launch_bounds__(256, 2)
gemm_fp16(const __half* __restrict__ A, const __half* __restrict__ Wt,
          const float* __restrict__ bias, const float* __restrict__ res,
          OUT* __restrict__ C, int M, int N, int K) {
    extern __shared__ char dsm[];
    uint32_t base = smem_u32(dsm);

    int tid = threadIdx.x;
    int warp = tid >> 5, lane = tid & 31;
    int wm = warp & 1;
    int wn = warp >> 1;
    int mrow = lane >> 2, kq = lane & 3;
    int m0 = blockIdx.y * 128, n0 = blockIdx.x * 128;

    int ch0 = tid, ch1 = tid + 256;
    int ar0 = ch0 >> 2, ac0 = (ch0 & 3) * 8;
    int ar1 = ch1 >> 2, ac1 = (ch1 & 3) * 8;
    const __half* agp0 = A + (size_t)(m0 + ar0) * K + ac0;
    const __half* agp1 = A + (size_t)(m0 + ar1) * K + ac1;
    const __half* bgp0 = Wt + (size_t)(n0 + ar0) * K + ac0;
    const __half* bgp1 = Wt + (size_t)(n0 + ar1) * K + ac1;
    uint32_t ad0 = base + ar0 * 80 + ac0 * 2;
    uint32_t ad1 = base + ar1 * 80 + ac1 * 2;
    uint32_t bd0 = ad0 + FNST * FSTG;
    uint32_t bd1 = ad1 + FNST * FSTG;

    float acc[4][4][4];
#pragma unroll
    for (int i = 0; i < 4; i++)
#pragma unroll
        for (int j = 0; j < 4; j++)
#pragma unroll
            for (int k = 0; k < 4; k++) acc[i][j][k] = 0.f;

    int nk = K / 32;
    auto issue = [&](int it) {
        if (it < nk) {
            int s = it & 3;
            int k0 = it * 32;
            cp_async16(ad0 + s * FSTG, agp0 + k0);
            cp_async16(ad1 + s * FSTG, agp1 + k0);
            cp_async16(bd0 + s * FSTG, bgp0 + k0);
            cp_async16(bd1 + s * FSTG, bgp1 + k0);
        }
        cp_commit();
    };
    issue(0); issue(1); issue(2);

    int lrow = lane & 15;
    int lcolB = (lane >> 4) * 16;

    for (int it = 0; it < nk; it++) {
        cp_wait2();
        __syncthreads();
        issue(it + 3);
        int s = it & 3;
        uint32_t aST = base + s * FSTG;
        uint32_t bST = aST + FNST * FSTG;
#pragma unroll
        for (int ks = 0; ks < 32; ks += 16) {
            uint32_t a[4][4], b[2][4];
#pragma unroll
            for (int fm = 0; fm < 4; fm++)
                ldsm_x4(a[fm], aST + (wm * 64 + fm * 16 + lrow) * 80 + ks * 2 + lcolB);
#pragma unroll
            for (int p = 0; p < 2; p++)
                ldsm_x4(b[p], bST + (wn * 32 + p * 16 + lrow) * 80 + ks * 2 + lcolB);
#pragma unroll
            for (int fm = 0; fm < 4; fm++)
#pragma unroll
                for (int fn = 0; fn < 4; fn++)
                    mma_fp16(acc[fm][fn], a[fm],
                             b[fn >> 1][fn & 1], b[fn >> 1][2 + (fn & 1)]);
        }
    }

#pragma unroll
    for (int fm = 0; fm < 4; fm++) {
#pragma unroll
        for (int fn = 0; fn < 4; fn++) {
            int mr = m0 + wm * 64 + fm * 16 + mrow;
            int nc = n0 + wn * 32 + fn * 8 + (kq << 1);
            float bx = bias[nc], by = bias[nc + 1];
            float v0 = acc[fm][fn][0] + bx;
            float v1 = acc[fm][fn][1] + by;
            float v2 = acc[fm][fn][2] + bx;
            float v3 = acc[fm][fn][3] + by;
            if (EPI == 1) {
                v0 += res[(size_t)mr * N + nc];
                v1 += res[(size_t)mr * N + nc + 1];
                v2 += res[(size_t)(mr + 8) * N + nc];
                v3 += res[(size_t)(mr + 8) * N + nc + 1];
            } else if (EPI == 2) {
                v0 = gelu_exact(v0); v1 = gelu_exact(v1);
                v2 = gelu_exact(v2); v3 = gelu_exact(v3);
            }
            store2(C + (size_t)mr * N + nc, v0, v1);
            store2(C + (size_t)(mr + 8) * N + nc, v2, v3);
        }
    }
}

// ---------------------------------------------------------------------------
// Flash attention, parity streams, full fp16 MMA datapath.
// Block = 4 warps, 64 stream-queries, key tiles of 32. Q/K/V raw fp16 in smem
// (pitch 72 halves = conflict-free ldmatrix); P stays in registers.
// ---------------------------------------------------------------------------
#define ATP 72   // smem pitch in halves (144 B)

__global__ void __launch_bounds__(128, 4)
attn_flash(const __half* __restrict__ qkv, __half* __restrict__ out) {
    __shared__ __half Qs[64 * ATP];
    __shared__ __half Ks[32 * ATP];
    __shared__ __half Vs[32 * ATP];

    int tid = threadIdx.x;
    int w = tid >> 5, lane = tid & 31;
    int mrow = lane >> 2;
    int kq = lane & 3;

    int qt0 = blockIdx.x * 64;
    int y = blockIdx.y;
    int p = y & 1, h = (y >> 1) & 15, b = y >> 5;

    // ---- load Q tile (scale 1/8 folded, exact in fp16) ----
    {
        int r = tid >> 1;
        int d0 = (tid & 1) * 32;
        int l = 2 * (qt0 + r) + p;
        const __half* src = qkv + ((size_t)(b * LL + l)) * (3 * DDIM) + h * HDIM + d0;
        __half* dst = Qs + r * ATP + d0;
        const __half2 sc = __float2half2_rn(0.125f);
#pragma unroll
        for (int i = 0; i < 4; i++) {
            uint4 v = reinterpret_cast<const uint4*>(src)[i];
            __half2* hv = reinterpret_cast<__half2*>(&v);
#pragma unroll
            for (int j = 0; j < 4; j++) hv[j] = __hmul2(hv[j], sc);
            reinterpret_cast<uint4*>(dst)[i] = v;
        }
    }
    __syncthreads();

    // ---- Q a-fragments (persist in regs) ----
    uint32_t qa[4][4];
    {
        uint32_t qb = smem_u32(Qs) + (w * 16 + (lane & 15)) * (ATP * 2) + (lane >> 4) * 16;
#pragma unroll
        for (int i = 0; i < 4; i++) ldsm_x4(qa[i], qb + i * 32);
    }

    float m_lo = -1e30f, m_hi = -1e30f, l_lo = 0.f, l_hi = 0.f;
    float o[8][4];
#pragma unroll
    for (int i = 0; i < 8; i++)
#pragma unroll
        for (int j = 0; j < 4; j++) o[i][j] = 0.f;

    int tq_lo = qt0 + 16 * w + mrow;
    int tq_hi = tq_lo + 8;

    // ldmatrix address bases
    uint32_t kaddr = smem_u32(Ks) + ((lane >> 4) * 8 + (lane & 7)) * (ATP * 2)
                     + ((lane >> 3) & 1) * 16;
    uint32_t vaddr = smem_u32(Vs) + (lane & 15) * (ATP * 2) + (lane >> 4) * 16;

    int ktbeg = qt0 - 256; if (ktbeg < 0) ktbeg = 0;
    for (int kt0 = ktbeg; kt0 <= qt0 + 32; kt0 += 32) {
        // ---- fill K,V tiles (raw fp16) ----
        {
            int c = tid >> 2;
            int d0 = (tid & 3) * 16;
            int lk = 2 * (kt0 + c) + p;
            const __half* kb = qkv + ((size_t)(b * LL + lk)) * (3 * DDIM) + DDIM + h * HDIM + d0;
            const __half* vb = kb + DDIM;
            uint4 k0 = reinterpret_cast<const uint4*>(kb)[0];
            uint4 k1 = reinterpret_cast<const uint4*>(kb)[1];
            uint4 v0 = reinterpret_cast<const uint4*>(vb)[0];
            uint4 v1 = reinterpret_cast<const uint4*>(vb)[1];
            reinterpret_cast<uint4*>(Ks + c * ATP + d0)[0] = k0;
            reinterpret_cast<uint4*>(Ks + c * ATP + d0)[1] = k1;
            reinterpret_cast<uint4*>(Vs + c * ATP + d0)[0] = v0;
            reinterpret_cast<uint4*>(Vs + c * ATP + d0)[1] = v1;
        }
        __syncthreads();

        // ---- S = Q K^T (16x32 per warp, fp16 k16) ----
        float s_acc[4][4];
#pragma unroll
        for (int fn = 0; fn < 4; fn++)
#pragma unroll
            for (int j = 0; j < 4; j++) s_acc[fn][j] = 0.f;
#pragma unroll
        for (int i = 0; i < 4; i++) {
            uint32_t kb0[4], kb1[4];
            ldsm_x4(kb0, kaddr + i * 32);                    // keys 0-15
            ldsm_x4(kb1, kaddr + 16 * (ATP * 2) + i * 32);   // keys 16-31
            mma_fp16(s_acc[0], qa[i], kb0[0], kb0[1]);
            mma_fp16(s_acc[1], qa[i], kb0[2], kb0[3]);
            mma_fp16(s_acc[2], qa[i], kb1[0], kb1[1]);
            mma_fp16(s_acc[3], qa[i], kb1[2], kb1[3]);
        }

        // ---- mask + online softmax (c-layout identical to before) ----
        float mt_lo = -1e30f, mt_hi = -1e30f;
#pragma unroll
        for (int fn = 0; fn < 4; fn++) {
#pragma unroll
            for (int j = 0; j < 2; j++) {
                int tk = kt0 + 8 * fn + 2 * kq + j;
                if (!(tk <= tq_lo && tq_lo - tk <= 256)) s_acc[fn][j] = -1e30f;
                if (!(tk <= tq_hi && tq_hi - tk <= 256)) s_acc[fn][2 + j] = -1e30f;
                mt_lo = fmaxf(mt_lo, s_acc[fn][j]);
                mt_hi = fmaxf(mt_hi, s_acc[fn][2 + j]);
            }
        }
        mt_lo = fmaxf(mt_lo, __shfl_xor_sync(~0u, mt_lo, 1));
        mt_lo = fmaxf(mt_lo, __shfl_xor_sync(~0u, mt_lo, 2));
        mt_hi = fmaxf(mt_hi, __shfl_xor_sync(~0u, mt_hi, 1));
        mt_hi = fmaxf(mt_hi, __shfl_xor_sync(~0u, mt_hi, 2));
        float mn_lo = fmaxf(m_lo, mt_lo);
        float mn_hi = fmaxf(m_hi, mt_hi);
        float cf_lo = __expf(m_lo - mn_lo);
        float cf_hi = __expf(m_hi - mn_hi);
        m_lo = mn_lo; m_hi = mn_hi;

        float rs_lo = 0.f, rs_hi = 0.f;
        float pf[4][4];
#pragma unroll
        for (int fn = 0; fn < 4; fn++) {
#pragma unroll
            for (int j = 0; j < 2; j++) {
                float plo = __expf(s_acc[fn][j] - mn_lo);
                if (s_acc[fn][j] < -1e29f) plo = 0.f;
                float phi = __expf(s_acc[fn][2 + j] - mn_hi);
                if (s_acc[fn][2 + j] < -1e29f) phi = 0.f;
                rs_lo += plo; rs_hi += phi;
                pf[fn][j] = plo;
                pf[fn][2 + j] = phi;
            }
        }
        rs_lo += __shfl_xor_sync(~0u, rs_lo, 1);
        rs_lo += __shfl_xor_sync(~0u, rs_lo, 2);
        rs_hi += __shfl_xor_sync(~0u, rs_hi, 1);
        rs_hi += __shfl_xor_sync(~0u, rs_hi, 2);
        l_lo = l_lo * cf_lo + rs_lo;
        l_hi = l_hi * cf_hi + rs_hi;
#pragma unroll
        for (int fd = 0; fd < 8; fd++) {
            o[fd][0] *= cf_lo; o[fd][1] *= cf_lo;
            o[fd][2] *= cf_hi; o[fd][3] *= cf_hi;
        }

        // ---- P a-fragments from registers (no smem) ----
        uint32_t pa[2][4];
#pragma unroll
        for (int kb = 0; kb < 2; kb++) {
            __half2 h0 = __floats2half2_rn(pf[2 * kb][0], pf[2 * kb][1]);
            __half2 h1 = __floats2half2_rn(pf[2 * kb][2], pf[2 * kb][3]);
            __half2 h2 = __floats2half2_rn(pf[2 * kb + 1][0], pf[2 * kb + 1][1]);
            __half2 h3 = __floats2half2_rn(pf[2 * kb + 1][2], pf[2 * kb + 1][3]);
            pa[kb][0] = *reinterpret_cast<uint32_t*>(&h0);
            pa[kb][1] = *reinterpret_cast<uint32_t*>(&h1);
            pa[kb][2] = *reinterpret_cast<uint32_t*>(&h2);
            pa[kb][3] = *reinterpret_cast<uint32_t*>(&h3);
        }

        // ---- O += P V (fp16 k16, V via ldmatrix.trans) ----
#pragma unroll
        for (int kb = 0; kb < 2; kb++) {
#pragma unroll
            for (int dp = 0; dp < 4; dp++) {
                uint32_t vb4[4];
                ldsm_x4_t(vb4, vaddr + kb * 16 * (ATP * 2) + dp * 32);
                mma_fp16(o[2 * dp], pa[kb], vb4[0], vb4[1]);
                mma_fp16(o[2 * dp + 1], pa[kb], vb4[2], vb4[3]);
            }
        }
        __syncthreads();
    }

    float inv_lo = 1.0f / l_lo;
    float inv_hi = 1.0f / l_hi;
    int llo = 2 * tq_lo + p;
    int lhi = 2 * tq_hi + p;
    __half* obl = out + ((size_t)(b * LL + llo)) * DDIM + h * HDIM;
    __half* obh = out + ((size_t)(b * LL + lhi)) * DDIM + h * HDIM;
#pragma unroll
    for (int fd = 0; fd < 8; fd++) {
        int d = 8 * fd + 2 * kq;
        store2(obl + d, o[fd][0] * inv_lo, o[fd][1] * inv_lo);
        store2(obh + d, o[fd][2] * inv_hi, o[fd][3] * inv_hi);
    }
}

// ---------------------------------------------------------------------------
// Launch
// ---------------------------------------------------------------------------
extern "C" void kernel_launch(void* const* d_in, const int* in_sizes, int n_in,
                              void* d_out, int out_size) {
    const float* x     = (const float*)d_in[0];
    const float* ln1_g = (const float*)d_in[1];
    const float* ln1_b = (const float*)d_in[2];
    const float* Wqkv  = (const float*)d_in[3];
    const float* bqkv  = (const float*)d_in[4];
    const float* Wout  = (const float*)d_in[5];
    const float* bout  = (const float*)d_in[6];
    const float* ln2_g = (const float*)d_in[7];
    const float* ln2_b = (const float*)d_in[8];
    const float* W1    = (const float*)d_in[9];
    const float* b1    = (const float*)d_in[10];
    const float* W2    = (const float*)d_in[11];
    const float* b2    = (const float*)d_in[12];
    float* out = (float*)d_out;

    __half *h, *qkv, *attn, *f, *wt;
    float *x1;
    cudaGetSymbolAddress((void**)&h, g_h);
    cudaGetSymbolAddress((void**)&qkv, g_qkv);
    cudaGetSymbolAddress((void**)&attn, g_attn);
    cudaGetSymbolAddress((void**)&x1, g_x1);
    cudaGetSymbolAddress((void**)&f, g_f);
    cudaGetSymbolAddress((void**)&wt, g_wt);

    static int smem_set = 0;
    if (!smem_set) {
        cudaFuncSetAttribute(gemm_fp16<0, __half>,
                             cudaFuncAttributeMaxDynamicSharedMemorySize, FSMEM);
        cudaFuncSetAttribute(gemm_fp16<1, float>,
                             cudaFuncAttributeMaxDynamicSharedMemorySize, FSMEM);
        cudaFuncSetAttribute(gemm_fp16<2, __half>,
                             cudaFuncAttributeMaxDynamicSharedMemorySize, FSMEM);
        smem_set = 1;
    }

    dim3 tb(32, 8);
    // 0. transpose weights (N-major, fp16)
    transpose_h<<<dim3(3 * DDIM / 32, DDIM / 32), tb>>>(Wqkv, wt + WT_QKV, DDIM, 3 * DDIM);
    transpose_h<<<dim3(DDIM / 32, DDIM / 32), tb>>>(Wout, wt + WT_OUT, DDIM, DDIM);
    transpose_h<<<dim3(4 * DDIM / 32, DDIM / 32), tb>>>(W1, wt + WT_W1, DDIM, 4 * DDIM);
    transpose_h<<<dim3(DDIM / 32, 4 * DDIM / 32), tb>>>(W2, wt + WT_W2, 4 * DDIM, DDIM);

    // 1. LN1
    ln_kernel<<<MM, 256>>>(x, ln1_g, ln1_b, h);
    // 2. QKV = h @ Wqkv + bqkv
    gemm_fp16<0, __half><<<dim3(24, 32), 256, FSMEM>>>(
        h, wt + WT_QKV, bqkv, nullptr, qkv, MM, 3 * DDIM, DDIM);
    // 3. attention
    attn_flash<<<dim3(16, 64), 128>>>(qkv, attn);
    // 4. x1 = x + attn @ Wout + bout
    gemm_fp16<1, float><<<dim3(8, 32), 256, FSMEM>>>(
        attn, wt + WT_OUT, bout, x, x1, MM, DDIM, DDIM);
    // 5. LN2
    ln_kernel<<<MM, 256>>>(x1, ln2_g, ln2_b, h);
    // 6. f = gelu(h @ W1 + b1)
    gemm_fp16<2, __half><<<dim3(32, 32), 256, FSMEM>>>(
        h, wt + WT_W1, b1, nullptr, f, MM, 4 * DDIM, DDIM);
    // 7. out = x1 + f @ W2 + b2
    gemm_fp16<1, float><<<dim3(8, 32), 256, FSMEM>>>(
        f, wt + WT_W2, b2, x1, out, MM, DDIM, 4 * DDIM);
}

// round 8
// speedup vs baseline: 4.4826x; 1.1774x over previous
#include <cuda_runtime.h>
#include <cuda_fp16.h>
#include <cstdint>
#include <math.h>

// Problem constants
#define BB 2
#define LL 2048
#define DDIM 1024
#define HH 16
#define HDIM 64
#define MM (BB*LL)          // 4096 rows
#define WIN 512
#define DIL 2

// Scratch (device globals; no allocation allowed)
__device__ __half g_h[(size_t)MM*DDIM];          // LN output (fp16)
__device__ __half g_qkv[(size_t)MM*3*DDIM];      // QKV (fp16)
__device__ __half g_attn[(size_t)MM*DDIM];       // attention output (fp16)
__device__ float  g_x1[(size_t)MM*DDIM];         // x + attn@Wout (fp32, residual)
__device__ __half g_f[(size_t)MM*4*DDIM];        // FFN hidden (fp16)
__device__ __half g_wt[(size_t)12582912];        // fp16 weights, SAME [K,N] layout
#define WT_QKV 0
#define WT_OUT 3145728
#define WT_W1  4194304
#define WT_W2  8388608
#define WT_END 12582912

__device__ __forceinline__ void mma_fp16(float d[4], const uint32_t a[4],
                                         uint32_t b0, uint32_t b1) {
    asm volatile(
        "mma.sync.aligned.m16n8k16.row.col.f32.f16.f16.f32 "
        "{%0,%1,%2,%3}, {%4,%5,%6,%7}, {%8,%9}, {%0,%1,%2,%3};\n"
        : "+f"(d[0]), "+f"(d[1]), "+f"(d[2]), "+f"(d[3])
        : "r"(a[0]), "r"(a[1]), "r"(a[2]), "r"(a[3]),
          "r"(b0), "r"(b1));
}

__device__ __forceinline__ void ldsm_x4(uint32_t r[4], uint32_t addr) {
    asm volatile("ldmatrix.sync.aligned.m8n8.x4.shared.b16 {%0,%1,%2,%3}, [%4];"
                 : "=r"(r[0]), "=r"(r[1]), "=r"(r[2]), "=r"(r[3]) : "r"(addr));
}
__device__ __forceinline__ void ldsm_x4_t(uint32_t r[4], uint32_t addr) {
    asm volatile("ldmatrix.sync.aligned.m8n8.x4.trans.shared.b16 {%0,%1,%2,%3}, [%4];"
                 : "=r"(r[0]), "=r"(r[1]), "=r"(r[2]), "=r"(r[3]) : "r"(addr));
}

__device__ __forceinline__ float gelu_exact(float x) {
    return 0.5f * x * (1.0f + erff(x * 0.70710678118654752f));
}

__device__ __forceinline__ void cp_async16(uint32_t smem_addr, const void* gptr) {
    asm volatile("cp.async.cg.shared.global [%0], [%1], 16;\n"
                 :: "r"(smem_addr), "l"(gptr));
}
__device__ __forceinline__ void cp_commit() {
    asm volatile("cp.async.commit_group;\n");
}
__device__ __forceinline__ void cp_wait2() {
    asm volatile("cp.async.wait_group 2;\n");
}
__device__ __forceinline__ void cp_wait1() {
    asm volatile("cp.async.wait_group 1;\n");
}
__device__ __forceinline__ uint32_t smem_u32(const void* p) {
    uint32_t a;
    asm("{ .reg .u64 t; cvta.to.shared.u64 t, %1; cvt.u32.u64 %0, t; }"
        : "=r"(a) : "l"(p));
    return a;
}

__device__ __forceinline__ void store2(__half* p, float a, float b) {
    *reinterpret_cast<__half2*>(p) = __floats2half2_rn(a, b);
}
__device__ __forceinline__ void store2(float* p, float a, float b) {
    *reinterpret_cast<float2*>(p) = make_float2(a, b);
}

// ---------------------------------------------------------------------------
// Fused weight convert (layout-preserving fp32 -> fp16), all 4 weights.
// 8 elems/thread; tensor boundaries are multiples of 8.
// ---------------------------------------------------------------------------
__global__ void convert_w(const float* __restrict__ s0, const float* __restrict__ s1,
                          const float* __restrict__ s2, const float* __restrict__ s3,
                          __half* __restrict__ dst) {
    size_t i = ((size_t)blockIdx.x * 256 + threadIdx.x) * 8;
    const float* src; size_t base;
    if (i < WT_OUT)      { src = s0; base = 0; }
    else if (i < WT_W1)  { src = s1; base = WT_OUT; }
    else if (i < WT_W2)  { src = s2; base = WT_W1; }
    else                 { src = s3; base = WT_W2; }
    float4 a = *reinterpret_cast<const float4*>(src + (i - base));
    float4 b = *reinterpret_cast<const float4*>(src + (i - base) + 4);
    __half2 h0 = __floats2half2_rn(a.x, a.y);
    __half2 h1 = __floats2half2_rn(a.z, a.w);
    __half2 h2 = __floats2half2_rn(b.x, b.y);
    __half2 h3 = __floats2half2_rn(b.z, b.w);
    uint4 pk;
    pk.x = *reinterpret_cast<uint32_t*>(&h0);
    pk.y = *reinterpret_cast<uint32_t*>(&h1);
    pk.z = *reinterpret_cast<uint32_t*>(&h2);
    pk.w = *reinterpret_cast<uint32_t*>(&h3);
    *reinterpret_cast<uint4*>(dst + i) = pk;
}

// ---------------------------------------------------------------------------
// LayerNorm: one block (256 threads) per row of 1024 floats -> fp16 out
// ---------------------------------------------------------------------------
__global__ void ln_kernel(const float* __restrict__ x, const float* __restrict__ g,
                          const float* __restrict__ b, __half* __restrict__ out) {
    int row = blockIdx.x;
    int t = threadIdx.x;
    const float4 xv = reinterpret_cast<const float4*>(x + (size_t)row * DDIM)[t];

    __shared__ float warp_s[8], warp_q[8];
    __shared__ float s_mu, s_r;

    float s = xv.x + xv.y + xv.z + xv.w;
    float q = xv.x*xv.x + xv.y*xv.y + xv.z*xv.z + xv.w*xv.w;
#pragma unroll
    for (int o = 16; o; o >>= 1) {
        s += __shfl_xor_sync(~0u, s, o);
        q += __shfl_xor_sync(~0u, q, o);
    }
    if ((t & 31) == 0) { warp_s[t >> 5] = s; warp_q[t >> 5] = q; }
    __syncthreads();
    if (t == 0) {
        float S = 0.f, Q = 0.f;
#pragma unroll
        for (int i = 0; i < 8; i++) { S += warp_s[i]; Q += warp_q[i]; }
        float mu = S * (1.0f / DDIM);
        float var = Q * (1.0f / DDIM) - mu * mu;
        s_mu = mu;
        s_r = rsqrtf(var + 1e-5f);
    }
    __syncthreads();
    float mu = s_mu, r = s_r;
    float4 gv = reinterpret_cast<const float4*>(g)[t];
    float4 bv = reinterpret_cast<const float4*>(b)[t];
    __half2 o01 = __floats2half2_rn((xv.x - mu) * r * gv.x + bv.x,
                                    (xv.y - mu) * r * gv.y + bv.y);
    __half2 o23 = __floats2half2_rn((xv.z - mu) * r * gv.z + bv.z,
                                    (xv.w - mu) * r * gv.w + bv.w);
    uint2 pk;
    pk.x = *reinterpret_cast<uint32_t*>(&o01);
    pk.y = *reinterpret_cast<uint32_t*>(&o23);
    *reinterpret_cast<uint2*>(out + (size_t)row * DDIM + t * 4) = pk;
}

// ---------------------------------------------------------------------------
// FP16 GEMM: C[M,N] = A[M,K] @ W[K,N] + bias  (W row-major fp16)
// EPI: 0=bias, 1=bias+residual, 2=bias+GELU.  OUT: __half or float.
// Block 128x128x32, 256 threads (2 CTA/SM), warp tile 64x32, m16n8k16.
// A: [128 m][32 k] pitch 80B (as before). B: [32 k][128 n] pitch 272B,
// fragments via ldmatrix.x4.trans (rows=k, cols=n) — mirrors attention V path.
// ---------------------------------------------------------------------------
#define ASTG 10240                    // A stage bytes: 128 rows * 80B
#define BSTG 8704                     // B stage bytes: 32 rows * 272B
#define FNST 4
#define FSMEM (FNST*(ASTG+BSTG))      // 75776 bytes

template <int EPI, typename OUT>
__global__ void __launch_bounds__(256, 2)
gemm_fp16(const __half* __restrict__ A, const __half* __restrict__ W,
          const float* __restrict__ bias, const float* __restrict__ res,
          OUT* __restrict__ C, int M, int N, int K) {
    extern __shared__ char dsm[];
    uint32_t base = smem_u32(dsm);
    uint32_t bBase = base + FNST * ASTG;

    int tid = threadIdx.x;
    int warp = tid >> 5, lane = tid & 31;
    int wm = warp & 1;
    int wn = warp >> 1;
    int mrow = lane >> 2, kq = lane & 3;
    int m0 = blockIdx.y * 128, n0 = blockIdx.x * 128;

    // A: 512 chunks of 16B (128 rows x 4); B: 512 chunks (32 rows x 16)
    int ar0 = tid >> 2, ac0 = (tid & 3) * 8;
    int ar1 = ar0 + 64;
    int br0 = tid >> 4, bc0 = (tid & 15) * 8;   // br0 in 0..15
    const __half* agp0 = A + (size_t)(m0 + ar0) * K + ac0;
    const __half* agp1 = A + (size_t)(m0 + ar1) * K + ac0;
    const __half* bgp0 = W + (size_t)br0 * N + n0 + bc0;
    const __half* bgp1 = W + (size_t)(br0 + 16) * N + n0 + bc0;
    uint32_t ad0 = base + ar0 * 80 + ac0 * 2;
    uint32_t ad1 = base + ar1 * 80 + ac0 * 2;
    uint32_t bd0 = bBase + br0 * 272 + bc0 * 2;
    uint32_t bd1 = bBase + (br0 + 16) * 272 + bc0 * 2;

    float acc[4][4][4];
#pragma unroll
    for (int i = 0; i < 4; i++)
#pragma unroll
        for (int j = 0; j < 4; j++)
#pragma unroll
            for (int k = 0; k < 4; k++) acc[i][j][k] = 0.f;

    int nk = K / 32;
    auto issue = [&](int it) {
        if (it < nk) {
            int s = it & 3;
            int k0 = it * 32;
            cp_async16(ad0 + s * ASTG, agp0 + k0);
            cp_async16(ad1 + s * ASTG, agp1 + k0);
            cp_async16(bd0 + s * BSTG, bgp0 + (size_t)k0 * N);
            cp_async16(bd1 + s * BSTG, bgp1 + (size_t)k0 * N);
        }
        cp_commit();
    };
    issue(0); issue(1); issue(2);

    int lrow = lane & 15;
    int lcolB = (lane >> 4) * 16;

    for (int it = 0; it < nk; it++) {
        cp_wait2();
        __syncthreads();
        issue(it + 3);
        int s = it & 3;
        uint32_t aST = base + s * ASTG;
        uint32_t bST = bBase + s * BSTG;
#pragma unroll
        for (int ks = 0; ks < 32; ks += 16) {
            uint32_t a[4][4], b[2][4];
#pragma unroll
            for (int fm = 0; fm < 4; fm++)
                ldsm_x4(a[fm], aST + (wm * 64 + fm * 16 + lrow) * 80 + ks * 2 + lcolB);
            // B fragments: rows = k (trans), cols = n
            uint32_t bRow = bST + (ks + lrow) * 272 + lcolB;
#pragma unroll
            for (int p = 0; p < 2; p++)
                ldsm_x4_t(b[p], bRow + (wn * 32 + p * 16) * 2);
#pragma unroll
            for (int fm = 0; fm < 4; fm++)
#pragma unroll
                for (int fn = 0; fn < 4; fn++)
                    mma_fp16(acc[fm][fn], a[fm],
                             b[fn >> 1][(fn & 1) * 2], b[fn >> 1][(fn & 1) * 2 + 1]);
        }
    }

#pragma unroll
    for (int fm = 0; fm < 4; fm++) {
#pragma unroll
        for (int fn = 0; fn < 4; fn++) {
            int mr = m0 + wm * 64 + fm * 16 + mrow;
            int nc = n0 + wn * 32 + fn * 8 + (kq << 1);
            float bx = bias[nc], by = bias[nc + 1];
            float v0 = acc[fm][fn][0] + bx;
            float v1 = acc[fm][fn][1] + by;
            float v2 = acc[fm][fn][2] + bx;
            float v3 = acc[fm][fn][3] + by;
            if (EPI == 1) {
                v0 += res[(size_t)mr * N + nc];
                v1 += res[(size_t)mr * N + nc + 1];
                v2 += res[(size_t)(mr + 8) * N + nc];
                v3 += res[(size_t)(mr + 8) * N + nc + 1];
            } else if (EPI == 2) {
                v0 = gelu_exact(v0); v1 = gelu_exact(v1);
                v2 = gelu_exact(v2); v3 = gelu_exact(v3);
            }
            store2(C + (size_t)mr * N + nc, v0, v1);
            store2(C + (size_t)(mr + 8) * N + nc, v2, v3);
        }
    }
}

// ---------------------------------------------------------------------------
// Flash attention, parity streams, fp16 MMA datapath, cp.async K/V pipeline.
// ---------------------------------------------------------------------------
#define ATP 72    // smem pitch in halves (144 B)
#define KVST (32 * ATP * 2)   // bytes per K (or V) tile buffer

__global__ void __launch_bounds__(128, 4)
attn_flash(const __half* __restrict__ qkv, __half* __restrict__ out) {
    __shared__ __half Qs[64 * ATP];
    __shared__ __half Ks[2][32 * ATP];
    __shared__ __half Vs[2][32 * ATP];

    int tid = threadIdx.x;
    int w = tid >> 5, lane = tid & 31;
    int mrow = lane >> 2;
    int kq = lane & 3;

    int qt0 = blockIdx.x * 64;
    int y = blockIdx.y;
    int p = y & 1, h = (y >> 1) & 15, b = y >> 5;

    // ---- load Q tile (scale 1/8 folded, exact in fp16) ----
    {
        int r = tid >> 1;
        int d0 = (tid & 1) * 32;
        int l = 2 * (qt0 + r) + p;
        const __half* src = qkv + ((size_t)(b * LL + l)) * (3 * DDIM) + h * HDIM + d0;
        __half* dst = Qs + r * ATP + d0;
        const __half2 sc = __float2half2_rn(0.125f);
#pragma unroll
        for (int i = 0; i < 4; i++) {
            uint4 v = reinterpret_cast<const uint4*>(src)[i];
            __half2* hv = reinterpret_cast<__half2*>(&v);
#pragma unroll
            for (int j = 0; j < 4; j++) hv[j] = __hmul2(hv[j], sc);
            reinterpret_cast<uint4*>(dst)[i] = v;
        }
    }

    int ktbeg = qt0 - 256; if (ktbeg < 0) ktbeg = 0;
    int nt = (qt0 + 32 - ktbeg) / 32 + 1;

    // K/V cp.async: 256 chunks of 16B each (32 rows x 8); 2 per thread
    int kvr0 = tid >> 3;              // 0..15
    int kvc = (tid & 7) * 16;         // byte offset within 128B row
    uint32_t ksb = smem_u32(Ks);
    uint32_t vsb = smem_u32(Vs);
    auto issue_kv = [&](int ti) {
        if (ti < nt) {
            int s = ti & 1;
            int kt0 = ktbeg + ti * 32;
#pragma unroll
            for (int half = 0; half < 2; half++) {
                int r = kvr0 + half * 16;
                int lk = 2 * (kt0 + r) + p;
                const __half* kb = qkv + ((size_t)(b * LL + lk)) * (3 * DDIM)
                                   + DDIM + h * HDIM;
                cp_async16(ksb + s * KVST + r * 144 + kvc,
                           reinterpret_cast<const char*>(kb) + kvc);
                cp_async16(vsb + s * KVST + r * 144 + kvc,
                           reinterpret_cast<const char*>(kb + DDIM) + kvc);
            }
        }
        cp_commit();
    };
    issue_kv(0);
    issue_kv(1);

    __syncthreads();   // Q tile ready

    // ---- Q a-fragments (persist in regs) ----
    uint32_t qa[4][4];
    {
        uint32_t qb = smem_u32(Qs) + (w * 16 + (lane & 15)) * (ATP * 2) + (lane >> 4) * 16;
#pragma unroll
        for (int i = 0; i < 4; i++) ldsm_x4(qa[i], qb + i * 32);
    }

    float m_lo = -1e30f, m_hi = -1e30f, l_lo = 0.f, l_hi = 0.f;
    float o[8][4];
#pragma unroll
    for (int i = 0; i < 8; i++)
#pragma unroll
        for (int j = 0; j < 4; j++) o[i][j] = 0.f;

    int tq_lo = qt0 + 16 * w + mrow;
    int tq_hi = tq_lo + 8;

    uint32_t kaddrO = ((lane >> 4) * 8 + (lane & 7)) * (ATP * 2) + ((lane >> 3) & 1) * 16;
    uint32_t vaddrO = (lane & 15) * (ATP * 2) + (lane >> 4) * 16;

    for (int ti = 0; ti < nt; ti++) {
        int kt0 = ktbeg + ti * 32;
        int s = ti & 1;
        cp_wait1();
        __syncthreads();
        uint32_t kaddr = ksb + s * KVST + kaddrO;
        uint32_t vaddr = vsb + s * KVST + vaddrO;

        // ---- S = Q K^T (16x32 per warp, fp16 k16) ----
        float s_acc[4][4];
#pragma unroll
        for (int fn = 0; fn < 4; fn++)
#pragma unroll
            for (int j = 0; j < 4; j++) s_acc[fn][j] = 0.f;
#pragma unroll
        for (int i = 0; i < 4; i++) {
            uint32_t kb0[4], kb1[4];
            ldsm_x4(kb0, kaddr + i * 32);
            ldsm_x4(kb1, kaddr + 16 * (ATP * 2) + i * 32);
            mma_fp16(s_acc[0], qa[i], kb0[0], kb0[1]);
            mma_fp16(s_acc[1], qa[i], kb0[2], kb0[3]);
            mma_fp16(s_acc[2], qa[i], kb1[0], kb1[1]);
            mma_fp16(s_acc[3], qa[i], kb1[2], kb1[3]);
        }

        // ---- mask + online softmax ----
        float mt_lo = -1e30f, mt_hi = -1e30f;
#pragma unroll
        for (int fn = 0; fn < 4; fn++) {
#pragma unroll
            for (int j = 0; j < 2; j++) {
                int tk = kt0 + 8 * fn + 2 * kq + j;
                if (!(tk <= tq_lo && tq_lo - tk <= 256)) s_acc[fn][j] = -1e30f;
                if (!(tk <= tq_hi && tq_hi - tk <= 256)) s_acc[fn][2 + j] = -1e30f;
                mt_lo = fmaxf(mt_lo, s_acc[fn][j]);
                mt_hi = fmaxf(mt_hi, s_acc[fn][2 + j]);
            }
        }
        mt_lo = fmaxf(mt_lo, __shfl_xor_sync(~0u, mt_lo, 1));
        mt_lo = fmaxf(mt_lo, __shfl_xor_sync(~0u, mt_lo, 2));
        mt_hi = fmaxf(mt_hi, __shfl_xor_sync(~0u, mt_hi, 1));
        mt_hi = fmaxf(mt_hi, __shfl_xor_sync(~0u, mt_hi, 2));
        float mn_lo = fmaxf(m_lo, mt_lo);
        float mn_hi = fmaxf(m_hi, mt_hi);
        float cf_lo = __expf(m_lo - mn_lo);
        float cf_hi = __expf(m_hi - mn_hi);
        m_lo = mn_lo; m_hi = mn_hi;

        float rs_lo = 0.f, rs_hi = 0.f;
        float pf[4][4];
#pragma unroll
        for (int fn = 0; fn < 4; fn++) {
#pragma unroll
            for (int j = 0; j < 2; j++) {
                float plo = __expf(s_acc[fn][j] - mn_lo);
                if (s_acc[fn][j] < -1e29f) plo = 0.f;
                float phi = __expf(s_acc[fn][2 + j] - mn_hi);
                if (s_acc[fn][2 + j] < -1e29f) phi = 0.f;
                rs_lo += plo; rs_hi += phi;
                pf[fn][j] = plo;
                pf[fn][2 + j] = phi;
            }
        }
        rs_lo += __shfl_xor_sync(~0u, rs_lo, 1);
        rs_lo += __shfl_xor_sync(~0u, rs_lo, 2);
        rs_hi += __shfl_xor_sync(~0u, rs_hi, 1);
        rs_hi += __shfl_xor_sync(~0u, rs_hi, 2);
        l_lo = l_lo * cf_lo + rs_lo;
        l_hi = l_hi * cf_hi + rs_hi;
#pragma unroll
        for (int fd = 0; fd < 8; fd++) {
            o[fd][0] *= cf_lo; o[fd][1] *= cf_lo;
            o[fd][2] *= cf_hi; o[fd][3] *= cf_hi;
        }

        // ---- P a-fragments from registers ----
        uint32_t pa[2][4];
#pragma unroll
        for (int kb = 0; kb < 2; kb++) {
            __half2 h0 = __floats2half2_rn(pf[2 * kb][0], pf[2 * kb][1]);
            __half2 h1 = __floats2half2_rn(pf[2 * kb][2], pf[2 * kb][3]);
            __half2 h2 = __floats2half2_rn(pf[2 * kb + 1][0], pf[2 * kb + 1][1]);
            __half2 h3 = __floats2half2_rn(pf[2 * kb + 1][2], pf[2 * kb + 1][3]);
            pa[kb][0] = *reinterpret_cast<uint32_t*>(&h0);
            pa[kb][1] = *reinterpret_cast<uint32_t*>(&h1);
            pa[kb][2] = *reinterpret_cast<uint32_t*>(&h2);
            pa[kb][3] = *reinterpret_cast<uint32_t*>(&h3);
        }

        // ---- O += P V ----
#pragma unroll
        for (int kb = 0; kb < 2; kb++) {
#pragma unroll
            for (int dp = 0; dp < 4; dp++) {
                uint32_t vb4[4];
                ldsm_x4_t(vb4, vaddr + kb * 16 * (ATP * 2) + dp * 32);
                mma_fp16(o[2 * dp], pa[kb], vb4[0], vb4[1]);
                mma_fp16(o[2 * dp + 1], pa[kb], vb4[2], vb4[3]);
            }
        }
        __syncthreads();
        issue_kv(ti + 2);
    }

    float inv_lo = 1.0f / l_lo;
    float inv_hi = 1.0f / l_hi;
    int llo = 2 * tq_lo + p;
    int lhi = 2 * tq_hi + p;
    __half* obl = out + ((size_t)(b * LL + llo)) * DDIM + h * HDIM;
    __half* obh = out + ((size_t)(b * LL + lhi)) * DDIM + h * HDIM;
#pragma unroll
    for (int fd = 0; fd < 8; fd++) {
        int d = 8 * fd + 2 * kq;
        store2(obl + d, o[fd][0] * inv_lo, o[fd][1] * inv_lo);
        store2(obh + d, o[fd][2] * inv_hi, o[fd][3] * inv_hi);
    }
}

// ---------------------------------------------------------------------------
// Launch
// ---------------------------------------------------------------------------
extern "C" void kernel_launch(void* const* d_in, const int* in_sizes, int n_in,
                              void* d_out, int out_size) {
    const float* x     = (const float*)d_in[0];
    const float* ln1_g = (const float*)d_in[1];
    const float* ln1_b = (const float*)d_in[2];
    const float* Wqkv  = (const float*)d_in[3];
    const float* bqkv  = (const float*)d_in[4];
    const float* Wout  = (const float*)d_in[5];
    const float* bout  = (const float*)d_in[6];
    const float* ln2_g = (const float*)d_in[7];
    const float* ln2_b = (const float*)d_in[8];
    const float* W1    = (const float*)d_in[9];
    const float* b1    = (const float*)d_in[10];
    const float* W2    = (const float*)d_in[11];
    const float* b2    = (const float*)d_in[12];
    float* out = (float*)d_out;

    __half *h, *qkv, *attn, *f, *wt;
    float *x1;
    cudaGetSymbolAddress((void**)&h, g_h);
    cudaGetSymbolAddress((void**)&qkv, g_qkv);
    cudaGetSymbolAddress((void**)&attn, g_attn);
    cudaGetSymbolAddress((void**)&x1, g_x1);
    cudaGetSymbolAddress((void**)&f, g_f);
    cudaGetSymbolAddress((void**)&wt, g_wt);

    static int smem_set = 0;
    if (!smem_set) {
        cudaFuncSetAttribute(gemm_fp16<0, __half>,
                             cudaFuncAttributeMaxDynamicSharedMemorySize, FSMEM);
        cudaFuncSetAttribute(gemm_fp16<1, float>,
                             cudaFuncAttributeMaxDynamicSharedMemorySize, FSMEM);
        cudaFuncSetAttribute(gemm_fp16<2, __half>,
                             cudaFuncAttributeMaxDynamicSharedMemorySize, FSMEM);
        smem_set = 1;
    }

    // 0. fp32 -> fp16 weight convert (layout preserved)
    convert_w<<<WT_END / 2048, 256>>>(Wqkv, Wout, W1, W2, wt);
    // 1. LN1
    ln_kernel<<<MM, 256>>>(x, ln1_g, ln1_b, h);
    // 2. QKV = h @ Wqkv + bqkv
    gemm_fp16<0, __half><<<dim3(24, 32), 256, FSMEM>>>(
        h, wt + WT_QKV, bqkv, nullptr, qkv, MM, 3 * DDIM, DDIM);
    // 3. attention
    attn_flash<<<dim3(16, 64), 128>>>(qkv, attn);
    // 4. x1 = x + attn @ Wout + bout
    gemm_fp16<1, float><<<dim3(8, 32), 256, FSMEM>>>(
        attn, wt + WT_OUT, bout, x, x1, MM, DDIM, DDIM);
    // 5. LN2
    ln_kernel<<<MM, 256>>>(x1, ln2_g, ln2_b, h);
    // 6. f = gelu(h @ W1 + b1)
    gemm_fp16<2, __half><<<dim3(32, 32), 256, FSMEM>>>(
        h, wt + WT_W1, b1, nullptr, f, MM, 4 * DDIM, DDIM);
    // 7. out = x1 + f @ W2 + b2
    gemm_fp16<1, float><<<dim3(8, 32), 256, FSMEM>>>(
        f, wt + WT_W2, b2, x1, out, MM, DDIM, 4 * DDIM);
}

// round 9
// speedup vs baseline: 4.7540x; 1.0606x over previous
#include <cuda_runtime.h>
#include <cuda_fp16.h>
#include <cstdint>
#include <math.h>

// Problem constants
#define BB 2
#define LL 2048
#define DDIM 1024
#define HH 16
#define HDIM 64
#define MM (BB*LL)          // 4096 rows
#define WIN 512
#define DIL 2

// Scratch (device globals; no allocation allowed)
__device__ __half g_h[(size_t)MM*DDIM];          // LN output (fp16)
__device__ __half g_qkv[(size_t)MM*3*DDIM];      // QKV (fp16)
__device__ __half g_attn[(size_t)MM*DDIM];       // attention output (fp16)
__device__ float  g_x1[(size_t)MM*DDIM];         // x + attn@Wout (fp32, residual)
__device__ __half g_f[(size_t)MM*4*DDIM];        // FFN hidden (fp16)
__device__ __half g_wt[(size_t)12582912];        // fp16 weights, SAME [K,N] layout
#define WT_QKV 0
#define WT_OUT 3145728
#define WT_W1  4194304
#define WT_W2  8388608
#define WT_END 12582912

__device__ __forceinline__ void mma_fp16(float d[4], const uint32_t a[4],
                                         uint32_t b0, uint32_t b1) {
    asm volatile(
        "mma.sync.aligned.m16n8k16.row.col.f32.f16.f16.f32 "
        "{%0,%1,%2,%3}, {%4,%5,%6,%7}, {%8,%9}, {%0,%1,%2,%3};\n"
        : "+f"(d[0]), "+f"(d[1]), "+f"(d[2]), "+f"(d[3])
        : "r"(a[0]), "r"(a[1]), "r"(a[2]), "r"(a[3]),
          "r"(b0), "r"(b1));
}

__device__ __forceinline__ void ldsm_x4(uint32_t r[4], uint32_t addr) {
    asm volatile("ldmatrix.sync.aligned.m8n8.x4.shared.b16 {%0,%1,%2,%3}, [%4];"
                 : "=r"(r[0]), "=r"(r[1]), "=r"(r[2]), "=r"(r[3]) : "r"(addr));
}
__device__ __forceinline__ void ldsm_x4_t(uint32_t r[4], uint32_t addr) {
    asm volatile("ldmatrix.sync.aligned.m8n8.x4.trans.shared.b16 {%0,%1,%2,%3}, [%4];"
                 : "=r"(r[0]), "=r"(r[1]), "=r"(r[2]), "=r"(r[3]) : "r"(addr));
}

__device__ __forceinline__ float gelu_exact(float x) {
    return 0.5f * x * (1.0f + erff(x * 0.70710678118654752f));
}

__device__ __forceinline__ void cp_async16(uint32_t smem_addr, const void* gptr) {
    asm volatile("cp.async.cg.shared.global [%0], [%1], 16;\n"
                 :: "r"(smem_addr), "l"(gptr));
}
__device__ __forceinline__ void cp_commit() {
    asm volatile("cp.async.commit_group;\n");
}
__device__ __forceinline__ void cp_wait2() {
    asm volatile("cp.async.wait_group 2;\n");
}
__device__ __forceinline__ void cp_wait1() {
    asm volatile("cp.async.wait_group 1;\n");
}
__device__ __forceinline__ uint32_t smem_u32(const void* p) {
    uint32_t a;
    asm("{ .reg .u64 t; cvta.to.shared.u64 t, %1; cvt.u32.u64 %0, t; }"
        : "=r"(a) : "l"(p));
    return a;
}

__device__ __forceinline__ void store2(__half* p, float a, float b) {
    *reinterpret_cast<__half2*>(p) = __floats2half2_rn(a, b);
}
__device__ __forceinline__ void store2(float* p, float a, float b) {
    *reinterpret_cast<float2*>(p) = make_float2(a, b);
}

// ---------------------------------------------------------------------------
// Fused weight convert (layout-preserving fp32 -> fp16), all 4 weights.
// ---------------------------------------------------------------------------
__global__ void convert_w(const float* __restrict__ s0, const float* __restrict__ s1,
                          const float* __restrict__ s2, const float* __restrict__ s3,
                          __half* __restrict__ dst) {
    size_t i = ((size_t)blockIdx.x * 256 + threadIdx.x) * 8;
    const float* src; size_t base;
    if (i < WT_OUT)      { src = s0; base = 0; }
    else if (i < WT_W1)  { src = s1; base = WT_OUT; }
    else if (i < WT_W2)  { src = s2; base = WT_W1; }
    else                 { src = s3; base = WT_W2; }
    float4 a = *reinterpret_cast<const float4*>(src + (i - base));
    float4 b = *reinterpret_cast<const float4*>(src + (i - base) + 4);
    __half2 h0 = __floats2half2_rn(a.x, a.y);
    __half2 h1 = __floats2half2_rn(a.z, a.w);
    __half2 h2 = __floats2half2_rn(b.x, b.y);
    __half2 h3 = __floats2half2_rn(b.z, b.w);
    uint4 pk;
    pk.x = *reinterpret_cast<uint32_t*>(&h0);
    pk.y = *reinterpret_cast<uint32_t*>(&h1);
    pk.z = *reinterpret_cast<uint32_t*>(&h2);
    pk.w = *reinterpret_cast<uint32_t*>(&h3);
    *reinterpret_cast<uint4*>(dst + i) = pk;
}

// ---------------------------------------------------------------------------
// LayerNorm: one block (256 threads) per row of 1024 floats -> fp16 out
// ---------------------------------------------------------------------------
__global__ void ln_kernel(const float* __restrict__ x, const float* __restrict__ g,
                          const float* __restrict__ b, __half* __restrict__ out) {
    int row = blockIdx.x;
    int t = threadIdx.x;
    const float4 xv = reinterpret_cast<const float4*>(x + (size_t)row * DDIM)[t];

    __shared__ float warp_s[8], warp_q[8];
    __shared__ float s_mu, s_r;

    float s = xv.x + xv.y + xv.z + xv.w;
    float q = xv.x*xv.x + xv.y*xv.y + xv.z*xv.z + xv.w*xv.w;
#pragma unroll
    for (int o = 16; o; o >>= 1) {
        s += __shfl_xor_sync(~0u, s, o);
        q += __shfl_xor_sync(~0u, q, o);
    }
    if ((t & 31) == 0) { warp_s[t >> 5] = s; warp_q[t >> 5] = q; }
    __syncthreads();
    if (t == 0) {
        float S = 0.f, Q = 0.f;
#pragma unroll
        for (int i = 0; i < 8; i++) { S += warp_s[i]; Q += warp_q[i]; }
        float mu = S * (1.0f / DDIM);
        float var = Q * (1.0f / DDIM) - mu * mu;
        s_mu = mu;
        s_r = rsqrtf(var + 1e-5f);
    }
    __syncthreads();
    float mu = s_mu, r = s_r;
    float4 gv = reinterpret_cast<const float4*>(g)[t];
    float4 bv = reinterpret_cast<const float4*>(b)[t];
    __half2 o01 = __floats2half2_rn((xv.x - mu) * r * gv.x + bv.x,
                                    (xv.y - mu) * r * gv.y + bv.y);
    __half2 o23 = __floats2half2_rn((xv.z - mu) * r * gv.z + bv.z,
                                    (xv.w - mu) * r * gv.w + bv.w);
    uint2 pk;
    pk.x = *reinterpret_cast<uint32_t*>(&o01);
    pk.y = *reinterpret_cast<uint32_t*>(&o23);
    *reinterpret_cast<uint2*>(out + (size_t)row * DDIM + t * 4) = pk;
}

// ---------------------------------------------------------------------------
// FP16 GEMM: C[M,N] = A[M,K] @ W[K,N] + bias  (W row-major fp16)
// EPI: 0=bias, 1=bias+residual, 2=bias+GELU.  OUT: __half or float.
// Block tile 128x128x32, **128 threads (4 warps), warp tile 64x64**, m16n8k16.
// A: [128 m][32 k] pitch 80B; B: [32 k][128 n] pitch 272B, ldmatrix.x4.trans.
// 4-stage cp.async pipeline, wait_group 2, one __syncthreads per K-iter.
// ---------------------------------------------------------------------------
#define ASTG 10240                    // A stage bytes: 128 rows * 80B
#define BSTG 8704                     // B stage bytes: 32 rows * 272B
#define FNST 4
#define FSMEM (FNST*(ASTG+BSTG))      // 75776 bytes

template <int EPI, typename OUT>
__global__ void __launch_bounds__(128, 2)
gemm_fp16(const __half* __restrict__ A, const __half* __restrict__ W,
          const float* __restrict__ bias, const float* __restrict__ res,
          OUT* __restrict__ C, int M, int N, int K) {
    extern __shared__ char dsm[];
    uint32_t base = smem_u32(dsm);
    uint32_t bBase = base + FNST * ASTG;

    int tid = threadIdx.x;
    int warp = tid >> 5, lane = tid & 31;
    int wm = warp & 1;     // 2 warps along M -> 64 rows
    int wn = warp >> 1;    // 2 warps along N -> 64 cols
    int mrow = lane >> 2, kq = lane & 3;
    int m0 = blockIdx.y * 128, n0 = blockIdx.x * 128;

    // cp.async: A 512 chunks (128 rows x 4), B 512 chunks (32 rows x 16); 4+4 per thread
    const __half* agp[4];
    const __half* bgp[4];
    uint32_t adst[4], bdst[4];
#pragma unroll
    for (int i = 0; i < 4; i++) {
        int ca = tid + i * 128;
        int ar = ca >> 2, ac = (ca & 3) * 8;
        agp[i] = A + (size_t)(m0 + ar) * K + ac;
        adst[i] = base + ar * 80 + ac * 2;
        int br = ca >> 4, bc = (ca & 15) * 8;
        bgp[i] = W + (size_t)br * N + n0 + bc;
        bdst[i] = bBase + br * 272 + bc * 2;
    }

    float acc[4][8][4];
#pragma unroll
    for (int i = 0; i < 4; i++)
#pragma unroll
        for (int j = 0; j < 8; j++)
#pragma unroll
            for (int k = 0; k < 4; k++) acc[i][j][k] = 0.f;

    int nk = K / 32;
    auto issue = [&](int it) {
        if (it < nk) {
            int s = it & 3;
            int k0 = it * 32;
#pragma unroll
            for (int i = 0; i < 4; i++) {
                cp_async16(adst[i] + s * ASTG, agp[i] + k0);
                cp_async16(bdst[i] + s * BSTG, bgp[i] + (size_t)k0 * N);
            }
        }
        cp_commit();
    };
    issue(0); issue(1); issue(2);

    int lrow = lane & 15;
    int lcolB = (lane >> 4) * 16;

    for (int it = 0; it < nk; it++) {
        cp_wait2();
        __syncthreads();
        issue(it + 3);
        int s = it & 3;
        uint32_t aST = base + s * ASTG;
        uint32_t bST = bBase + s * BSTG;
#pragma unroll
        for (int ks = 0; ks < 32; ks += 16) {
            uint32_t a[4][4], b[4][4];
#pragma unroll
            for (int fm = 0; fm < 4; fm++)
                ldsm_x4(a[fm], aST + (wm * 64 + fm * 16 + lrow) * 80 + ks * 2 + lcolB);
            uint32_t bRow = bST + (ks + lrow) * 272 + lcolB;
#pragma unroll
            for (int p = 0; p < 4; p++)
                ldsm_x4_t(b[p], bRow + (wn * 64 + p * 16) * 2);
#pragma unroll
            for (int fm = 0; fm < 4; fm++)
#pragma unroll
                for (int fn = 0; fn < 8; fn++)
                    mma_fp16(acc[fm][fn], a[fm],
                             b[fn >> 1][(fn & 1) * 2], b[fn >> 1][(fn & 1) * 2 + 1]);
        }
    }

#pragma unroll
    for (int fm = 0; fm < 4; fm++) {
#pragma unroll
        for (int fn = 0; fn < 8; fn++) {
            int mr = m0 + wm * 64 + fm * 16 + mrow;
            int nc = n0 + wn * 64 + fn * 8 + (kq << 1);
            float bx = bias[nc], by = bias[nc + 1];
            float v0 = acc[fm][fn][0] + bx;
            float v1 = acc[fm][fn][1] + by;
            float v2 = acc[fm][fn][2] + bx;
            float v3 = acc[fm][fn][3] + by;
            if (EPI == 1) {
                v0 += res[(size_t)mr * N + nc];
                v1 += res[(size_t)mr * N + nc + 1];
                v2 += res[(size_t)(mr + 8) * N + nc];
                v3 += res[(size_t)(mr + 8) * N + nc + 1];
            } else if (EPI == 2) {
                v0 = gelu_exact(v0); v1 = gelu_exact(v1);
                v2 = gelu_exact(v2); v3 = gelu_exact(v3);
            }
            store2(C + (size_t)mr * N + nc, v0, v1);
            store2(C + (size_t)(mr + 8) * N + nc, v2, v3);
        }
    }
}

// ---------------------------------------------------------------------------
// Flash attention, parity streams, fp16 MMA datapath, cp.async K/V pipeline.
// (unchanged from round 8)
// ---------------------------------------------------------------------------
#define ATP 72    // smem pitch in halves (144 B)
#define KVST (32 * ATP * 2)   // bytes per K (or V) tile buffer

__global__ void __launch_bounds__(128, 4)
attn_flash(const __half* __restrict__ qkv, __half* __restrict__ out) {
    __shared__ __half Qs[64 * ATP];
    __shared__ __half Ks[2][32 * ATP];
    __shared__ __half Vs[2][32 * ATP];

    int tid = threadIdx.x;
    int w = tid >> 5, lane = tid & 31;
    int mrow = lane >> 2;
    int kq = lane & 3;

    int qt0 = blockIdx.x * 64;
    int y = blockIdx.y;
    int p = y & 1, h = (y >> 1) & 15, b = y >> 5;

    {
        int r = tid >> 1;
        int d0 = (tid & 1) * 32;
        int l = 2 * (qt0 + r) + p;
        const __half* src = qkv + ((size_t)(b * LL + l)) * (3 * DDIM) + h * HDIM + d0;
        __half* dst = Qs + r * ATP + d0;
        const __half2 sc = __float2half2_rn(0.125f);
#pragma unroll
        for (int i = 0; i < 4; i++) {
            uint4 v = reinterpret_cast<const uint4*>(src)[i];
            __half2* hv = reinterpret_cast<__half2*>(&v);
#pragma unroll
            for (int j = 0; j < 4; j++) hv[j] = __hmul2(hv[j], sc);
            reinterpret_cast<uint4*>(dst)[i] = v;
        }
    }

    int ktbeg = qt0 - 256; if (ktbeg < 0) ktbeg = 0;
    int nt = (qt0 + 32 - ktbeg) / 32 + 1;

    int kvr0 = tid >> 3;
    int kvc = (tid & 7) * 16;
    uint32_t ksb = smem_u32(Ks);
    uint32_t vsb = smem_u32(Vs);
    auto issue_kv = [&](int ti) {
        if (ti < nt) {
            int s = ti & 1;
            int kt0 = ktbeg + ti * 32;
#pragma unroll
            for (int half = 0; half < 2; half++) {
                int r = kvr0 + half * 16;
                int lk = 2 * (kt0 + r) + p;
                const __half* kb = qkv + ((size_t)(b * LL + lk)) * (3 * DDIM)
                                   + DDIM + h * HDIM;
                cp_async16(ksb + s * KVST + r * 144 + kvc,
                           reinterpret_cast<const char*>(kb) + kvc);
                cp_async16(vsb + s * KVST + r * 144 + kvc,
                           reinterpret_cast<const char*>(kb + DDIM) + kvc);
            }
        }
        cp_commit();
    };
    issue_kv(0);
    issue_kv(1);

    __syncthreads();

    uint32_t qa[4][4];
    {
        uint32_t qb = smem_u32(Qs) + (w * 16 + (lane & 15)) * (ATP * 2) + (lane >> 4) * 16;
#pragma unroll
        for (int i = 0; i < 4; i++) ldsm_x4(qa[i], qb + i * 32);
    }

    float m_lo = -1e30f, m_hi = -1e30f, l_lo = 0.f, l_hi = 0.f;
    float o[8][4];
#pragma unroll
    for (int i = 0; i < 8; i++)
#pragma unroll
        for (int j = 0; j < 4; j++) o[i][j] = 0.f;

    int tq_lo = qt0 + 16 * w + mrow;
    int tq_hi = tq_lo + 8;

    uint32_t kaddrO = ((lane >> 4) * 8 + (lane & 7)) * (ATP * 2) + ((lane >> 3) & 1) * 16;
    uint32_t vaddrO = (lane & 15) * (ATP * 2) + (lane >> 4) * 16;

    for (int ti = 0; ti < nt; ti++) {
        int kt0 = ktbeg + ti * 32;
        int s = ti & 1;
        cp_wait1();
        __syncthreads();
        uint32_t kaddr = ksb + s * KVST + kaddrO;
        uint32_t vaddr = vsb + s * KVST + vaddrO;

        float s_acc[4][4];
#pragma unroll
        for (int fn = 0; fn < 4; fn++)
#pragma unroll
            for (int j = 0; j < 4; j++) s_acc[fn][j] = 0.f;
#pragma unroll
        for (int i = 0; i < 4; i++) {
            uint32_t kb0[4], kb1[4];
            ldsm_x4(kb0, kaddr + i * 32);
            ldsm_x4(kb1, kaddr + 16 * (ATP * 2) + i * 32);
            mma_fp16(s_acc[0], qa[i], kb0[0], kb0[1]);
            mma_fp16(s_acc[1], qa[i], kb0[2], kb0[3]);
            mma_fp16(s_acc[2], qa[i], kb1[0], kb1[1]);
            mma_fp16(s_acc[3], qa[i], kb1[2], kb1[3]);
        }

        float mt_lo = -1e30f, mt_hi = -1e30f;
#pragma unroll
        for (int fn = 0; fn < 4; fn++) {
#pragma unroll
            for (int j = 0; j < 2; j++) {
                int tk = kt0 + 8 * fn + 2 * kq + j;
                if (!(tk <= tq_lo && tq_lo - tk <= 256)) s_acc[fn][j] = -1e30f;
                if (!(tk <= tq_hi && tq_hi - tk <= 256)) s_acc[fn][2 + j] = -1e30f;
                mt_lo = fmaxf(mt_lo, s_acc[fn][j]);
                mt_hi = fmaxf(mt_hi, s_acc[fn][2 + j]);
            }
        }
        mt_lo = fmaxf(mt_lo, __shfl_xor_sync(~0u, mt_lo, 1));
        mt_lo = fmaxf(mt_lo, __shfl_xor_sync(~0u, mt_lo, 2));
        mt_hi = fmaxf(mt_hi, __shfl_xor_sync(~0u, mt_hi, 1));
        mt_hi = fmaxf(mt_hi, __shfl_xor_sync(~0u, mt_hi, 2));
        float mn_lo = fmaxf(m_lo, mt_lo);
        float mn_hi = fmaxf(m_hi, mt_hi);
        float cf_lo = __expf(m_lo - mn_lo);
        float cf_hi = __expf(m_hi - mn_hi);
        m_lo = mn_lo; m_hi = mn_hi;

        float rs_lo = 0.f, rs_hi = 0.f;
        float pf[4][4];
#pragma unroll
        for (int fn = 0; fn < 4; fn++) {
#pragma unroll
            for (int j = 0; j < 2; j++) {
                float plo = __expf(s_acc[fn][j] - mn_lo);
                if (s_acc[fn][j] < -1e29f) plo = 0.f;
                float phi = __expf(s_acc[fn][2 + j] - mn_hi);
                if (s_acc[fn][2 + j] < -1e29f) phi = 0.f;
                rs_lo += plo; rs_hi += phi;
                pf[fn][j] = plo;
                pf[fn][2 + j] = phi;
            }
        }
        rs_lo += __shfl_xor_sync(~0u, rs_lo, 1);
        rs_lo += __shfl_xor_sync(~0u, rs_lo, 2);
        rs_hi += __shfl_xor_sync(~0u, rs_hi, 1);
        rs_hi += __shfl_xor_sync(~0u, rs_hi, 2);
        l_lo = l_lo * cf_lo + rs_lo;
        l_hi = l_hi * cf_hi + rs_hi;
#pragma unroll
        for (int fd = 0; fd < 8; fd++) {
            o[fd][0] *= cf_lo; o[fd][1] *= cf_lo;
            o[fd][2] *= cf_hi; o[fd][3] *= cf_hi;
        }

        uint32_t pa[2][4];
#pragma unroll
        for (int kb = 0; kb < 2; kb++) {
            __half2 h0 = __floats2half2_rn(pf[2 * kb][0], pf[2 * kb][1]);
            __half2 h1 = __floats2half2_rn(pf[2 * kb][2], pf[2 * kb][3]);
            __half2 h2 = __floats2half2_rn(pf[2 * kb + 1][0], pf[2 * kb + 1][1]);
            __half2 h3 = __floats2half2_rn(pf[2 * kb + 1][2], pf[2 * kb + 1][3]);
            pa[kb][0] = *reinterpret_cast<uint32_t*>(&h0);
            pa[kb][1] = *reinterpret_cast<uint32_t*>(&h1);
            pa[kb][2] = *reinterpret_cast<uint32_t*>(&h2);
            pa[kb][3] = *reinterpret_cast<uint32_t*>(&h3);
        }

#pragma unroll
        for (int kb = 0; kb < 2; kb++) {
#pragma unroll
            for (int dp = 0; dp < 4; dp++) {
                uint32_t vb4[4];
                ldsm_x4_t(vb4, vaddr + kb * 16 * (ATP * 2) + dp * 32);
                mma_fp16(o[2 * dp], pa[kb], vb4[0], vb4[1]);
                mma_fp16(o[2 * dp + 1], pa[kb], vb4[2], vb4[3]);
            }
        }
        __syncthreads();
        issue_kv(ti + 2);
    }

    float inv_lo = 1.0f / l_lo;
    float inv_hi = 1.0f / l_hi;
    int llo = 2 * tq_lo + p;
    int lhi = 2 * tq_hi + p;
    __half* obl = out + ((size_t)(b * LL + llo)) * DDIM + h * HDIM;
    __half* obh = out + ((size_t)(b * LL + lhi)) * DDIM + h * HDIM;
#pragma unroll
    for (int fd = 0; fd < 8; fd++) {
        int d = 8 * fd + 2 * kq;
        store2(obl + d, o[fd][0] * inv_lo, o[fd][1] * inv_lo);
        store2(obh + d, o[fd][2] * inv_hi, o[fd][3] * inv_hi);
    }
}

// ---------------------------------------------------------------------------
// Launch
// ---------------------------------------------------------------------------
extern "C" void kernel_launch(void* const* d_in, const int* in_sizes, int n_in,
                              void* d_out, int out_size) {
    const float* x     = (const float*)d_in[0];
    const float* ln1_g = (const float*)d_in[1];
    const float* ln1_b = (const float*)d_in[2];
    const float* Wqkv  = (const float*)d_in[3];
    const float* bqkv  = (const float*)d_in[4];
    const float* Wout  = (const float*)d_in[5];
    const float* bout  = (const float*)d_in[6];
    const float* ln2_g = (const float*)d_in[7];
    const float* ln2_b = (const float*)d_in[8];
    const float* W1    = (const float*)d_in[9];
    const float* b1    = (const float*)d_in[10];
    const float* W2    = (const float*)d_in[11];
    const float* b2    = (const float*)d_in[12];
    float* out = (float*)d_out;

    __half *h, *qkv, *attn, *f, *wt;
    float *x1;
    cudaGetSymbolAddress((void**)&h, g_h);
    cudaGetSymbolAddress((void**)&qkv, g_qkv);
    cudaGetSymbolAddress((void**)&attn, g_attn);
    cudaGetSymbolAddress((void**)&x1, g_x1);
    cudaGetSymbolAddress((void**)&f, g_f);
    cudaGetSymbolAddress((void**)&wt, g_wt);

    static int smem_set = 0;
    if (!smem_set) {
        cudaFuncSetAttribute(gemm_fp16<0, __half>,
                             cudaFuncAttributeMaxDynamicSharedMemorySize, FSMEM);
        cudaFuncSetAttribute(gemm_fp16<1, float>,
                             cudaFuncAttributeMaxDynamicSharedMemorySize, FSMEM);
        cudaFuncSetAttribute(gemm_fp16<2, __half>,
                             cudaFuncAttributeMaxDynamicSharedMemorySize, FSMEM);
        smem_set = 1;
    }

    // 0. fp32 -> fp16 weight convert (layout preserved)
    convert_w<<<WT_END / 2048, 256>>>(Wqkv, Wout, W1, W2, wt);
    // 1. LN1
    ln_kernel<<<MM, 256>>>(x, ln1_g, ln1_b, h);
    // 2. QKV = h @ Wqkv + bqkv
    gemm_fp16<0, __half><<<dim3(24, 32), 128, FSMEM>>>(
        h, wt + WT_QKV, bqkv, nullptr, qkv, MM, 3 * DDIM, DDIM);
    // 3. attention
    attn_flash<<<dim3(16, 64), 128>>>(qkv, attn);
    // 4. x1 = x + attn @ Wout + bout
    gemm_fp16<1, float><<<dim3(8, 32), 128, FSMEM>>>(
        attn, wt + WT_OUT, bout, x, x1, MM, DDIM, DDIM);
    // 5. LN2
    ln_kernel<<<MM, 256>>>(x1, ln2_g, ln2_b, h);
    // 6. f = gelu(h @ W1 + b1)
    gemm_fp16<2, __half><<<dim3(32, 32), 128, FSMEM>>>(
        h, wt + WT_W1, b1, nullptr, f, MM, 4 * DDIM, DDIM);
    // 7. out = x1 + f @ W2 + b2
    gemm_fp16<1, float><<<dim3(8, 32), 128, FSMEM>>>(
        f, wt + WT_W2, b2, x1, out, MM, DDIM, 4 * DDIM);
}